// round 2
// baseline (speedup 1.0000x reference)
#include <cuda_runtime.h>
#include <float.h>
#include <stdint.h>

// Problem constants
#define Bsz 16
#define Npt 4096
#define Cft 64
#define Mc  1024
#define Kn  64
#define Hd  128
#define CIN 67   // C+3

// ---------------- scratch (device globals; no allocation allowed) --------
__device__ int   g_idx[Bsz*Mc];
__device__ int   g_nbr[Bsz*Mc*Kn];
__device__ int   g_cnt[Bsz*Mc];
__device__ float g_ctr[Bsz*Mc*3];
__device__ float g_poss_dump[Bsz*Mc*3];  // fallback if out buffer has no pos_s region

typedef unsigned long long ull;

// ---------------- f32x2 helpers ------------------------------------------
__device__ __forceinline__ ull fma2(ull a, ull b, ull c) {
    ull d;
    asm("fma.rn.f32x2 %0, %1, %2, %3;" : "=l"(d) : "l"(a), "l"(b), "l"(c));
    return d;
}
__device__ __forceinline__ ull dup2(float x) {
    ull d;
    unsigned xi = __float_as_uint(x);
    asm("mov.b64 %0, {%1, %2};" : "=l"(d) : "r"(xi), "r"(xi));
    return d;
}
__device__ __forceinline__ void unpk(ull v, float& lo, float& hi) {
    unsigned a, b;
    asm("mov.b64 {%0, %1}, %2;" : "=r"(a), "=r"(b) : "l"(v));
    lo = __uint_as_float(a);
    hi = __uint_as_float(b);
}

// ============================ 1) FPS ======================================
// One block per batch, 1024 threads, 4 points/thread in registers.
// Positions cached in smem for the per-step broadcast read.
// Argmax: value-max via u32 redux (dists>=0 so float bits are monotonic),
// then first matching index via equality scan + atomicMin (== jnp.argmax
// first-occurrence semantics, bit-exact).
#define FPS_T 1024
#define FPPT 4

extern __shared__ float fps_sm[];

__global__ __launch_bounds__(FPS_T) void fps_kernel(const float* __restrict__ pos) {
    float* spx = fps_sm;            // 4096
    float* spy = spx + Npt;         // 4096
    float* spz = spy + Npt;         // 4096
    __shared__ unsigned swv[32];
    __shared__ unsigned s_vmax;
    __shared__ int s_idx;

    int b = blockIdx.x;
    const float* p = pos + b * Npt * 3;
    int t = threadIdx.x;
    int lane = t & 31;
    int w = t >> 5;

    float px[FPPT], py[FPPT], pz[FPPT], dd[FPPT];
#pragma unroll
    for (int j = 0; j < FPPT; j++) {
        int i = t + j * FPS_T;
        float xx = p[i * 3 + 0];
        float yy = p[i * 3 + 1];
        float zz = p[i * 3 + 2];
        px[j] = xx; py[j] = yy; pz[j] = zz;
        spx[i] = xx; spy[i] = yy; spz[i] = zz;
        dd[j] = FLT_MAX;
    }
    if (t == 0) { g_idx[b * Mc] = 0; s_idx = 0x7fffffff; }
    __syncthreads();

    int last = 0;
    for (int s = 1; s < Mc; s++) {
        float lx = spx[last], ly = spy[last], lz = spz[last];
        unsigned vmx = 0u;
#pragma unroll
        for (int j = 0; j < FPPT; j++) {
            float dx = __fsub_rn(px[j], lx);
            float dy = __fsub_rn(py[j], ly);
            float dz = __fsub_rn(pz[j], lz);
            float d  = __fadd_rn(__fadd_rn(__fmul_rn(dx, dx), __fmul_rn(dy, dy)),
                                 __fmul_rn(dz, dz));
            float v = fminf(dd[j], d);
            dd[j] = v;
            unsigned vu = __float_as_uint(v);
            vmx = vmx > vu ? vmx : vu;
        }
        unsigned wmax = __reduce_max_sync(0xffffffffu, vmx);
        if (lane == 0) swv[w] = wmax;
        __syncthreads();
        if (t < 32) {
            unsigned v = __reduce_max_sync(0xffffffffu, swv[t]);
            if (t == 0) { s_vmax = v; s_idx = 0x7fffffff; }
        }
        __syncthreads();
        float vm = __uint_as_float(s_vmax);
#pragma unroll
        for (int j = 0; j < FPPT; j++) {
            if (dd[j] == vm) atomicMin(&s_idx, t + j * FPS_T);
        }
        __syncthreads();
        last = s_idx;
        if (t == 0) g_idx[b * Mc + s] = last;
    }
}

// ============================ 2) radius query =============================
// One warp per center: first Kn in-radius neighbors in index order.
// d2 = (sn + pn) - 2*dot, all non-fused (unchanged from passing version).
#define QWARPS 8

__global__ __launch_bounds__(QWARPS * 32) void query_kernel(
    const float* __restrict__ pos, float* __restrict__ poss_out) {
    int cm   = blockIdx.x * QWARPS + (threadIdx.x >> 5);
    int lane = threadIdx.x & 31;
    int b    = cm >> 10;  // cm / Mc
    const float* p = pos + b * Npt * 3;

    int   ci = g_idx[cm];
    float sx = p[ci * 3 + 0], sy = p[ci * 3 + 1], sz = p[ci * 3 + 2];
    if (lane == 0) {
        poss_out[cm * 3 + 0] = sx;
        poss_out[cm * 3 + 1] = sy;
        poss_out[cm * 3 + 2] = sz;
        g_ctr[cm * 3 + 0] = sx;
        g_ctr[cm * 3 + 1] = sy;
        g_ctr[cm * 3 + 2] = sz;
    }
    float sn = __fadd_rn(__fadd_rn(__fmul_rn(sx, sx), __fmul_rn(sy, sy)),
                         __fmul_rn(sz, sz));
    const float R2 = 0.2f * 0.2f;

    int cnt = 0;
    for (int base = 0; base < Npt; base += 32) {
        int   i = base + lane;
        float xx = p[i * 3 + 0], yy = p[i * 3 + 1], zz = p[i * 3 + 2];
        float pn = __fadd_rn(__fadd_rn(__fmul_rn(xx, xx), __fmul_rn(yy, yy)),
                             __fmul_rn(zz, zz));
        float dot = __fadd_rn(__fadd_rn(__fmul_rn(sx, xx), __fmul_rn(sy, yy)),
                              __fmul_rn(sz, zz));
        float d2 = __fsub_rn(__fadd_rn(sn, pn), __fmul_rn(2.0f, dot));
        bool  in = (d2 <= R2);
        unsigned ball = __ballot_sync(0xffffffffu, in);
        if (in) {
            int ppos = cnt + __popc(ball & ((1u << lane) - 1u));
            if (ppos < Kn) g_nbr[cm * Kn + ppos] = i;
        }
        cnt += __popc(ball);
        if (cnt >= Kn) break;
    }
    if (cnt > Kn) cnt = Kn;
    for (int k = cnt + lane; k < Kn; k += 32) g_nbr[cm * Kn + k] = 0;
    if (lane == 0) g_cnt[cm] = cnt;
}

// ============================ 3) MLP + masked max =========================
// Persistent blocks (1/SM), 512 threads (16 warps). Weights staged once.
// Per center: gather feat[64][68] -> layer1 (f32x2) -> h1[64][132]
// -> layer2 (f32x2) -> relu -> masked max over k -> out row.
// Each thread: 2 rows x 8 cols, k-loop unrolled x4 with vector smem loads.
#define MLP_T 512
#define LDC 68    // feat row pitch (floats)
#define LDH 132   // h1 row pitch (floats)

#define SMEM_FLOATS (CIN*Hd + Hd*Hd + Hd + Hd + Kn*LDC + Kn*LDH + 32*Hd)
#define SMEM_BYTES  (SMEM_FLOATS * 4 + Kn * 4)

extern __shared__ float smem[];

__global__ __launch_bounds__(MLP_T, 1) void mlp_kernel(
    const float* __restrict__ x, const float* __restrict__ pos,
    const float* __restrict__ W1, const float* __restrict__ b1,
    const float* __restrict__ W2, const float* __restrict__ b2,
    float* __restrict__ out) {
    float* W1s  = smem;                    // 67*128
    float* W2s  = W1s + CIN * Hd;          // 128*128
    float* b1s  = W2s + Hd * Hd;           // 128
    float* b2s  = b1s + Hd;                // 128
    float* feat = b2s + Hd;                // 64*68
    float* h1s  = feat + Kn * LDC;         // 64*132
    float* smax = h1s + Kn * LDH;          // 32*128
    int*   snbr = (int*)(smax + 32 * Hd);  // 64
    __shared__ int s_cnt;

    int tid = threadIdx.x;
    for (int i = tid; i < CIN * Hd; i += MLP_T) W1s[i] = W1[i];
    for (int i = tid; i < Hd * Hd; i += MLP_T) W2s[i] = W2[i];
    if (tid < Hd) { b1s[tid] = b1[tid]; b2s[tid] = b2[tid]; }

    int ty   = tid >> 4;    // 0..31
    int tx   = tid & 15;    // 0..15
    int row0 = ty * 2;
    int col0 = tx * 8;

    for (int cm = blockIdx.x; cm < Bsz * Mc; cm += gridDim.x) {
        int b = cm >> 10;
        __syncthreads();  // weights ready (1st iter) / previous center done
        if (tid < Kn) snbr[tid] = g_nbr[cm * Kn + tid];
        if (tid == 0) s_cnt = g_cnt[cm];
        __syncthreads();
        int cnt = s_cnt;

        // gather x features -> feat[k][c] (row-major, pitch LDC)
        const float* xb = x + (size_t)b * Npt * Cft;
#pragma unroll
        for (int j = tid; j < (Kn * Cft) / 4; j += MLP_T) {
            int k  = j >> 4;
            int c4 = (j & 15) * 4;
            float4 v = *(const float4*)(xb + (size_t)snbr[k] * Cft + c4);
            *(float4*)(feat + k * LDC + c4) = v;
        }
        // pos diffs -> feat[k][64..66]
        if (tid < Kn) {
            float cx = g_ctr[cm * 3 + 0], cy = g_ctr[cm * 3 + 1], cz = g_ctr[cm * 3 + 2];
            const float* pb = pos + b * Npt * 3;
            int n3 = snbr[tid] * 3;
            feat[tid * LDC + 64] = pb[n3 + 0] - cx;
            feat[tid * LDC + 65] = pb[n3 + 1] - cy;
            feat[tid * LDC + 66] = pb[n3 + 2] - cz;
        }
        __syncthreads();

        ull acc[2][4];
#pragma unroll
        for (int r = 0; r < 2; r++)
#pragma unroll
            for (int q = 0; q < 4; q++) acc[r][q] = 0ULL;

        bool live = (row0 < cnt);

        // -------- layer 1: feat[64x67] @ W1[67x128] ----------
        if (live) {
            const float* a0p = feat + row0 * LDC;
            const float* a1p = a0p + LDC;
            for (int c = 0; c < 64; c += 4) {
                float av0[4], av1[4];
                *(float4*)av0 = *(const float4*)(a0p + c);
                *(float4*)av1 = *(const float4*)(a1p + c);
#pragma unroll
                for (int q = 0; q < 4; q++) {
                    const float* wrow = W1s + (c + q) * Hd + col0;
                    ulonglong2 wA = *(const ulonglong2*)(wrow);
                    ulonglong2 wB = *(const ulonglong2*)(wrow + 4);
                    ull d0 = dup2(av0[q]);
                    ull d1 = dup2(av1[q]);
                    acc[0][0] = fma2(d0, wA.x, acc[0][0]);
                    acc[0][1] = fma2(d0, wA.y, acc[0][1]);
                    acc[0][2] = fma2(d0, wB.x, acc[0][2]);
                    acc[0][3] = fma2(d0, wB.y, acc[0][3]);
                    acc[1][0] = fma2(d1, wA.x, acc[1][0]);
                    acc[1][1] = fma2(d1, wA.y, acc[1][1]);
                    acc[1][2] = fma2(d1, wB.x, acc[1][2]);
                    acc[1][3] = fma2(d1, wB.y, acc[1][3]);
                }
            }
#pragma unroll
            for (int c = 64; c < CIN; c++) {
                const float* wrow = W1s + c * Hd + col0;
                ulonglong2 wA = *(const ulonglong2*)(wrow);
                ulonglong2 wB = *(const ulonglong2*)(wrow + 4);
                ull d0 = dup2(a0p[c]);
                ull d1 = dup2(a1p[c]);
                acc[0][0] = fma2(d0, wA.x, acc[0][0]);
                acc[0][1] = fma2(d0, wA.y, acc[0][1]);
                acc[0][2] = fma2(d0, wB.x, acc[0][2]);
                acc[0][3] = fma2(d0, wB.y, acc[0][3]);
                acc[1][0] = fma2(d1, wA.x, acc[1][0]);
                acc[1][1] = fma2(d1, wA.y, acc[1][1]);
                acc[1][2] = fma2(d1, wB.x, acc[1][2]);
                acc[1][3] = fma2(d1, wB.y, acc[1][3]);
            }
            // bias + relu + store h1 (rows are warp-private -> no block bar)
#pragma unroll
            for (int r = 0; r < 2; r++) {
                float f[8];
                unpk(acc[r][0], f[0], f[1]);
                unpk(acc[r][1], f[2], f[3]);
                unpk(acc[r][2], f[4], f[5]);
                unpk(acc[r][3], f[6], f[7]);
                float4 v0, v1;
                v0.x = fmaxf(f[0] + b1s[col0 + 0], 0.f);
                v0.y = fmaxf(f[1] + b1s[col0 + 1], 0.f);
                v0.z = fmaxf(f[2] + b1s[col0 + 2], 0.f);
                v0.w = fmaxf(f[3] + b1s[col0 + 3], 0.f);
                v1.x = fmaxf(f[4] + b1s[col0 + 4], 0.f);
                v1.y = fmaxf(f[5] + b1s[col0 + 5], 0.f);
                v1.z = fmaxf(f[6] + b1s[col0 + 6], 0.f);
                v1.w = fmaxf(f[7] + b1s[col0 + 7], 0.f);
                *(float4*)(h1s + (row0 + r) * LDH + col0)     = v0;
                *(float4*)(h1s + (row0 + r) * LDH + col0 + 4) = v1;
            }
        }
        __syncwarp();

        // -------- layer 2: h1[64x128] @ W2[128x128] ----------
#pragma unroll
        for (int r = 0; r < 2; r++)
#pragma unroll
            for (int q = 0; q < 4; q++) acc[r][q] = 0ULL;

        if (live) {
            const float* a0p = h1s + row0 * LDH;
            const float* a1p = a0p + LDH;
            for (int h = 0; h < Hd; h += 4) {
                float av0[4], av1[4];
                *(float4*)av0 = *(const float4*)(a0p + h);
                *(float4*)av1 = *(const float4*)(a1p + h);
#pragma unroll
                for (int q = 0; q < 4; q++) {
                    const float* wrow = W2s + (h + q) * Hd + col0;
                    ulonglong2 wA = *(const ulonglong2*)(wrow);
                    ulonglong2 wB = *(const ulonglong2*)(wrow + 4);
                    ull d0 = dup2(av0[q]);
                    ull d1 = dup2(av1[q]);
                    acc[0][0] = fma2(d0, wA.x, acc[0][0]);
                    acc[0][1] = fma2(d0, wA.y, acc[0][1]);
                    acc[0][2] = fma2(d0, wB.x, acc[0][2]);
                    acc[0][3] = fma2(d0, wB.y, acc[0][3]);
                    acc[1][0] = fma2(d1, wA.x, acc[1][0]);
                    acc[1][1] = fma2(d1, wA.y, acc[1][1]);
                    acc[1][2] = fma2(d1, wB.x, acc[1][2]);
                    acc[1][3] = fma2(d1, wB.y, acc[1][3]);
                }
            }
        }

        // -------- bias + relu + masked max over this thread's rows -------
        float cmax[8];
#pragma unroll
        for (int q = 0; q < 8; q++) cmax[q] = -1e30f;
        if (live) {
            int rmax = cnt - row0;
            if (rmax > 2) rmax = 2;
            for (int r = 0; r < rmax; r++) {
                float f[8];
                unpk(acc[r][0], f[0], f[1]);
                unpk(acc[r][1], f[2], f[3]);
                unpk(acc[r][2], f[4], f[5]);
                unpk(acc[r][3], f[6], f[7]);
#pragma unroll
                for (int q = 0; q < 8; q++) {
                    float hv = fmaxf(f[q] + b2s[col0 + q], 0.f);
                    cmax[q]  = fmaxf(cmax[q], hv);
                }
            }
        }
        {
            float4 v0, v1;
            v0.x = cmax[0]; v0.y = cmax[1]; v0.z = cmax[2]; v0.w = cmax[3];
            v1.x = cmax[4]; v1.y = cmax[5]; v1.z = cmax[6]; v1.w = cmax[7];
            *(float4*)(smax + ty * Hd + col0)     = v0;
            *(float4*)(smax + ty * Hd + col0 + 4) = v1;
        }
        __syncthreads();
        if (tid < Hd) {
            float mv = -1e30f;
#pragma unroll
            for (int yy = 0; yy < 32; yy++) mv = fmaxf(mv, smax[yy * Hd + tid]);
            out[(size_t)cm * Hd + tid] = (cnt > 0) ? mv : 0.0f;
        }
    }
}

// ============================ launch ======================================
extern "C" void kernel_launch(void* const* d_in, const int* in_sizes, int n_in,
                              void* d_out, int out_size) {
    const float* x   = (const float*)d_in[0];
    const float* pos = (const float*)d_in[1];
    const float* W1  = (const float*)d_in[2];
    const float* b1  = (const float*)d_in[3];
    const float* W2  = (const float*)d_in[4];
    const float* b2  = (const float*)d_in[5];
    float* out = (float*)d_out;

    // tuple output layout: out [B*M*H] then pos_s [B*M*3]; guard against
    // a layout mismatch so we never write OOB.
    float* poss;
    if (out_size >= Bsz * Mc * (Hd + 3)) {
        poss = out + (size_t)Bsz * Mc * Hd;
    } else {
        void* tmp = nullptr;
        cudaGetSymbolAddress(&tmp, g_poss_dump);
        poss = (float*)tmp;
    }

    static int configured = 0;
    cudaFuncSetAttribute(mlp_kernel, cudaFuncAttributeMaxDynamicSharedMemorySize,
                         SMEM_BYTES);
    cudaFuncSetAttribute(fps_kernel, cudaFuncAttributeMaxDynamicSharedMemorySize,
                         3 * Npt * 4);
    (void)configured;

    fps_kernel<<<Bsz, FPS_T, 3 * Npt * 4>>>(pos);
    query_kernel<<<(Bsz * Mc) / QWARPS, QWARPS * 32>>>(pos, poss);
    mlp_kernel<<<152, MLP_T, SMEM_BYTES>>>(x, pos, W1, b1, W2, b2, out);
}

// round 3
// speedup vs baseline: 1.0258x; 1.0258x over previous
#include <cuda_runtime.h>
#include <float.h>
#include <stdint.h>

// Problem constants
#define Bsz 16
#define Npt 4096
#define Cft 64
#define Mc  1024
#define Kn  64
#define Hd  128
#define CIN 67   // C+3

// ---------------- scratch (device globals; no allocation allowed) --------
__device__ int   g_idx[Bsz*Mc];
__device__ int   g_nbr[Bsz*Mc*Kn];
__device__ int   g_cnt[Bsz*Mc];
__device__ float g_ctr[Bsz*Mc*3];
__device__ float g_poss_dump[Bsz*Mc*3];  // fallback if out buffer has no pos_s region

typedef unsigned long long ull;

// ---------------- f32x2 helpers ------------------------------------------
__device__ __forceinline__ ull fma2(ull a, ull b, ull c) {
    ull d;
    asm("fma.rn.f32x2 %0, %1, %2, %3;" : "=l"(d) : "l"(a), "l"(b), "l"(c));
    return d;
}
__device__ __forceinline__ ull dup2(float x) {
    ull d;
    unsigned xi = __float_as_uint(x);
    asm("mov.b64 %0, {%1, %2};" : "=l"(d) : "r"(xi), "r"(xi));
    return d;
}
__device__ __forceinline__ void unpk(ull v, float& lo, float& hi) {
    unsigned a, b;
    asm("mov.b64 {%0, %1}, %2;" : "=r"(a), "=r"(b) : "l"(v));
    lo = __uint_as_float(a);
    hi = __uint_as_float(b);
}

// ============================ 1) FPS ======================================
// One block per batch, 1024 threads, 4 points/thread in registers.
// Per step: warp max (u32 redux; dists>=0 so float bits monotonic),
// leaders -> swv[32]; ONE barrier; every warp redundantly reduces the 32
// warp maxes (no second shared round-trip); first-index recovery via
// equality + atomicMin into a ping-pong slot (== jnp.argmax first-
// occurrence, bit-exact); ONE barrier; read.
#define FPS_T 1024
#define FPPT 4

extern __shared__ float fps_sm[];

__global__ __launch_bounds__(FPS_T) void fps_kernel(const float* __restrict__ pos) {
    float* spx = fps_sm;            // 4096
    float* spy = spx + Npt;         // 4096
    float* spz = spy + Npt;         // 4096
    __shared__ unsigned swv[32];
    __shared__ int s_idx[2];

    int b = blockIdx.x;
    const float* p = pos + b * Npt * 3;
    int t = threadIdx.x;
    int lane = t & 31;
    int w = t >> 5;

    float px[FPPT], py[FPPT], pz[FPPT], dd[FPPT];
#pragma unroll
    for (int j = 0; j < FPPT; j++) {
        int i = t + j * FPS_T;
        float xx = p[i * 3 + 0];
        float yy = p[i * 3 + 1];
        float zz = p[i * 3 + 2];
        px[j] = xx; py[j] = yy; pz[j] = zz;
        spx[i] = xx; spy[i] = yy; spz[i] = zz;
        dd[j] = FLT_MAX;
    }
    if (t == 0) { g_idx[b * Mc] = 0; s_idx[0] = 0x7fffffff; s_idx[1] = 0x7fffffff; }
    __syncthreads();

    int last = 0;
    int par  = 0;
    for (int s = 1; s < Mc; s++) {
        float lx = spx[last], ly = spy[last], lz = spz[last];
        unsigned vmx = 0u;
#pragma unroll
        for (int j = 0; j < FPPT; j++) {
            float dx = __fsub_rn(px[j], lx);
            float dy = __fsub_rn(py[j], ly);
            float dz = __fsub_rn(pz[j], lz);
            float d  = __fadd_rn(__fadd_rn(__fmul_rn(dx, dx), __fmul_rn(dy, dy)),
                                 __fmul_rn(dz, dz));
            float v = fminf(dd[j], d);
            dd[j] = v;
            unsigned vu = __float_as_uint(v);
            vmx = vmx > vu ? vmx : vu;
        }
        unsigned wmax = __reduce_max_sync(0xffffffffu, vmx);
        if (lane == 0) swv[w] = wmax;
        __syncthreads();
        // every warp reduces the 32 warp-maxes redundantly
        unsigned vm_u = __reduce_max_sync(0xffffffffu, swv[lane]);
        float vm = __uint_as_float(vm_u);
        int cand = 0x7fffffff;
#pragma unroll
        for (int j = FPPT - 1; j >= 0; j--) {
            if (dd[j] == vm) cand = t + j * FPS_T;  // smallest j wins (last assign)
        }
        if (cand != 0x7fffffff) atomicMin(&s_idx[par], cand);
        if (t == 0) s_idx[par ^ 1] = 0x7fffffff;    // reset slot for next step
        __syncthreads();
        last = s_idx[par];
        par ^= 1;
        if (t == 0) g_idx[b * Mc + s] = last;
    }
}

// ============================ 2) radius query =============================
// One warp per center: first Kn in-radius neighbors in index order.
// d2 = (sn + pn) - 2*dot, all non-fused (unchanged, bit-identical).
#define QWARPS 8

__global__ __launch_bounds__(QWARPS * 32) void query_kernel(
    const float* __restrict__ pos, float* __restrict__ poss_out) {
    int cm   = blockIdx.x * QWARPS + (threadIdx.x >> 5);
    int lane = threadIdx.x & 31;
    int b    = cm >> 10;  // cm / Mc
    const float* p = pos + b * Npt * 3;

    int   ci = g_idx[cm];
    float sx = p[ci * 3 + 0], sy = p[ci * 3 + 1], sz = p[ci * 3 + 2];
    if (lane == 0) {
        poss_out[cm * 3 + 0] = sx;
        poss_out[cm * 3 + 1] = sy;
        poss_out[cm * 3 + 2] = sz;
        g_ctr[cm * 3 + 0] = sx;
        g_ctr[cm * 3 + 1] = sy;
        g_ctr[cm * 3 + 2] = sz;
    }
    float sn = __fadd_rn(__fadd_rn(__fmul_rn(sx, sx), __fmul_rn(sy, sy)),
                         __fmul_rn(sz, sz));
    const float R2 = 0.2f * 0.2f;

    int cnt = 0;
    for (int base = 0; base < Npt; base += 32) {
        int   i = base + lane;
        float xx = p[i * 3 + 0], yy = p[i * 3 + 1], zz = p[i * 3 + 2];
        float pn = __fadd_rn(__fadd_rn(__fmul_rn(xx, xx), __fmul_rn(yy, yy)),
                             __fmul_rn(zz, zz));
        float dot = __fadd_rn(__fadd_rn(__fmul_rn(sx, xx), __fmul_rn(sy, yy)),
                              __fmul_rn(sz, zz));
        float d2 = __fsub_rn(__fadd_rn(sn, pn), __fmul_rn(2.0f, dot));
        bool  in = (d2 <= R2);
        unsigned ball = __ballot_sync(0xffffffffu, in);
        if (in) {
            int ppos = cnt + __popc(ball & ((1u << lane) - 1u));
            if (ppos < Kn) g_nbr[cm * Kn + ppos] = i;
        }
        cnt += __popc(ball);
        if (cnt >= Kn) break;
    }
    if (cnt > Kn) cnt = Kn;
    for (int k = cnt + lane; k < Kn; k += 32) g_nbr[cm * Kn + k] = 0;
    if (lane == 0) g_cnt[cm] = cnt;
}

// ============================ 3) MLP + masked max =========================
// Persistent blocks (1/SM), 256 threads = 2 teams x 128, each team handles
// one center. Thread tile 4 rows x 16 cols (32 ull accumulators).
// Row-major feat/h1 (coalesced gather, broadcast-dedup A loads).
// Per warp per k-step: 4 scalar A (1 wf each) + 4 LDS.128 W (1 wf each)
// feeding 32 fma2 -> LDS well under the FMA2-issue floor.
#define MLP_T 256
#define LDC 68    // feat row pitch (floats)
#define LDH 132   // h1 row pitch (floats)

#define SMEM_FLOATS (CIN*Hd + Hd*Hd + Hd + Hd + 2*Kn*LDC + 2*Kn*LDH + 2*16*Hd)
#define SMEM_BYTES  (SMEM_FLOATS * 4 + 2 * Kn * 4 + 32)

extern __shared__ float smem[];

__global__ __launch_bounds__(MLP_T, 1) void mlp_kernel(
    const float* __restrict__ x, const float* __restrict__ pos,
    const float* __restrict__ W1, const float* __restrict__ b1,
    const float* __restrict__ W2, const float* __restrict__ b2,
    float* __restrict__ out) {
    float* W1s  = smem;                       // 67*128
    float* W2s  = W1s + CIN * Hd;             // 128*128
    float* b1s  = W2s + Hd * Hd;              // 128
    float* b2s  = b1s + Hd;                   // 128
    float* featb = b2s + Hd;                  // 2 * 64*68
    float* h1b   = featb + 2 * Kn * LDC;      // 2 * 64*132
    float* smaxb = h1b + 2 * Kn * LDH;        // 2 * 16*128
    int*   snbrb = (int*)(smaxb + 2 * 16 * Hd); // 2*64
    __shared__ int s_cnt[2];

    int tid = threadIdx.x;
    for (int i = tid; i < CIN * Hd; i += MLP_T) W1s[i] = W1[i];
    for (int i = tid; i < Hd * Hd; i += MLP_T) W2s[i] = W2[i];
    if (tid < Hd) { b1s[tid] = b1[tid]; b2s[tid] = b2[tid]; }

    int team = tid >> 7;        // 0/1
    int ttid = tid & 127;
    int tx   = ttid & 7;        // col group: 16 cols
    int ty   = ttid >> 3;       // row group: 4 rows, 0..15
    int row0 = ty * 4;
    int col0 = tx * 16;

    float* feat = featb + team * Kn * LDC;
    float* h1s  = h1b   + team * Kn * LDH;
    float* smax = smaxb + team * 16 * Hd;
    int*   snbr = snbrb + team * Kn;

    for (int base = blockIdx.x * 2; base < Bsz * Mc; base += gridDim.x * 2) {
        int cm = base + team;
        int b  = cm >> 10;
        __syncthreads();  // weights ready (1st iter) / previous center done
        if (ttid < Kn) snbr[ttid] = g_nbr[cm * Kn + ttid];
        if (ttid == Kn) s_cnt[team] = g_cnt[cm];
        __syncthreads();
        int cnt = s_cnt[team];

        // gather x features -> feat[k][c] (row-major, pitch LDC)
        const float* xb = x + (size_t)b * Npt * Cft;
#pragma unroll
        for (int j = ttid; j < Kn * 16; j += 128) {
            int k  = j >> 4;
            int c4 = (j & 15) << 2;
            float4 v = *(const float4*)(xb + (size_t)snbr[k] * Cft + c4);
            *(float4*)(feat + k * LDC + c4) = v;
        }
        // pos diffs -> feat[k][64..66]
        if (ttid < Kn) {
            float cx = g_ctr[cm * 3 + 0], cy = g_ctr[cm * 3 + 1], cz = g_ctr[cm * 3 + 2];
            const float* pb = pos + b * Npt * 3;
            int n3 = snbr[ttid] * 3;
            feat[ttid * LDC + 64] = pb[n3 + 0] - cx;
            feat[ttid * LDC + 65] = pb[n3 + 1] - cy;
            feat[ttid * LDC + 66] = pb[n3 + 2] - cz;
        }
        __syncthreads();

        bool live = (row0 < cnt);
        ull acc[4][8];
#pragma unroll
        for (int r = 0; r < 4; r++)
#pragma unroll
            for (int q = 0; q < 8; q++) acc[r][q] = 0ULL;

        // -------- layer 1: feat[64x67] @ W1[67x128] ----------
        if (live) {
            const float* a0 = feat + row0 * LDC;
#pragma unroll 4
            for (int c = 0; c < CIN; c++) {
                ull da0 = dup2(a0[c]);
                ull da1 = dup2(a0[LDC + c]);
                ull da2 = dup2(a0[2 * LDC + c]);
                ull da3 = dup2(a0[3 * LDC + c]);
                const float* wrow = W1s + c * Hd + col0;
                ulonglong2 w01 = *(const ulonglong2*)(wrow);
                ulonglong2 w23 = *(const ulonglong2*)(wrow + 4);
                ulonglong2 w45 = *(const ulonglong2*)(wrow + 8);
                ulonglong2 w67 = *(const ulonglong2*)(wrow + 12);
                ull wv[8] = {w01.x, w01.y, w23.x, w23.y, w45.x, w45.y, w67.x, w67.y};
#pragma unroll
                for (int q = 0; q < 8; q++) {
                    acc[0][q] = fma2(da0, wv[q], acc[0][q]);
                    acc[1][q] = fma2(da1, wv[q], acc[1][q]);
                    acc[2][q] = fma2(da2, wv[q], acc[2][q]);
                    acc[3][q] = fma2(da3, wv[q], acc[3][q]);
                }
            }
            // bias + relu + store h1 rows (consumed within this warp only)
#pragma unroll
            for (int r = 0; r < 4; r++) {
                float f[16];
#pragma unroll
                for (int q = 0; q < 8; q++) unpk(acc[r][q], f[2 * q], f[2 * q + 1]);
                float* hrow = h1s + (row0 + r) * LDH + col0;
#pragma unroll
                for (int v4 = 0; v4 < 4; v4++) {
                    float4 v;
                    v.x = fmaxf(f[v4 * 4 + 0] + b1s[col0 + v4 * 4 + 0], 0.f);
                    v.y = fmaxf(f[v4 * 4 + 1] + b1s[col0 + v4 * 4 + 1], 0.f);
                    v.z = fmaxf(f[v4 * 4 + 2] + b1s[col0 + v4 * 4 + 2], 0.f);
                    v.w = fmaxf(f[v4 * 4 + 3] + b1s[col0 + v4 * 4 + 3], 0.f);
                    *(float4*)(hrow + v4 * 4) = v;
                }
            }
        }
        __syncwarp();  // h1 rows row0..row0+3 written & read inside this warp

        // -------- layer 2: h1[64x128] @ W2[128x128] ----------
#pragma unroll
        for (int r = 0; r < 4; r++)
#pragma unroll
            for (int q = 0; q < 8; q++) acc[r][q] = 0ULL;

        if (live) {
            const float* a0 = h1s + row0 * LDH;
#pragma unroll 4
            for (int h = 0; h < Hd; h++) {
                ull da0 = dup2(a0[h]);
                ull da1 = dup2(a0[LDH + h]);
                ull da2 = dup2(a0[2 * LDH + h]);
                ull da3 = dup2(a0[3 * LDH + h]);
                const float* wrow = W2s + h * Hd + col0;
                ulonglong2 w01 = *(const ulonglong2*)(wrow);
                ulonglong2 w23 = *(const ulonglong2*)(wrow + 4);
                ulonglong2 w45 = *(const ulonglong2*)(wrow + 8);
                ulonglong2 w67 = *(const ulonglong2*)(wrow + 12);
                ull wv[8] = {w01.x, w01.y, w23.x, w23.y, w45.x, w45.y, w67.x, w67.y};
#pragma unroll
                for (int q = 0; q < 8; q++) {
                    acc[0][q] = fma2(da0, wv[q], acc[0][q]);
                    acc[1][q] = fma2(da1, wv[q], acc[1][q]);
                    acc[2][q] = fma2(da2, wv[q], acc[2][q]);
                    acc[3][q] = fma2(da3, wv[q], acc[3][q]);
                }
            }
        }

        // -------- bias + relu + masked max over this thread's rows -------
        float cmax[16];
#pragma unroll
        for (int q = 0; q < 16; q++) cmax[q] = -1e30f;
        if (live) {
            int rmax = cnt - row0;
            if (rmax > 4) rmax = 4;
            for (int r = 0; r < rmax; r++) {
                float f[16];
#pragma unroll
                for (int q = 0; q < 8; q++) unpk(acc[r][q], f[2 * q], f[2 * q + 1]);
#pragma unroll
                for (int q = 0; q < 16; q++) {
                    float hv = fmaxf(f[q] + b2s[col0 + q], 0.f);
                    cmax[q]  = fmaxf(cmax[q], hv);
                }
            }
        }
        {
            float* srow = smax + ty * Hd + col0;
#pragma unroll
            for (int v4 = 0; v4 < 4; v4++) {
                float4 v;
                v.x = cmax[v4 * 4 + 0]; v.y = cmax[v4 * 4 + 1];
                v.z = cmax[v4 * 4 + 2]; v.w = cmax[v4 * 4 + 3];
                *(float4*)(srow + v4 * 4) = v;
            }
        }
        __syncthreads();
        // final reduce: each team thread handles one output channel
        if (ttid < Hd) {
            float mv = -1e30f;
#pragma unroll
            for (int yy = 0; yy < 16; yy++) mv = fmaxf(mv, smax[yy * Hd + ttid]);
            out[(size_t)cm * Hd + ttid] = (cnt > 0) ? mv : 0.0f;
        }
    }
}

// ============================ launch ======================================
extern "C" void kernel_launch(void* const* d_in, const int* in_sizes, int n_in,
                              void* d_out, int out_size) {
    const float* x   = (const float*)d_in[0];
    const float* pos = (const float*)d_in[1];
    const float* W1  = (const float*)d_in[2];
    const float* b1  = (const float*)d_in[3];
    const float* W2  = (const float*)d_in[4];
    const float* b2  = (const float*)d_in[5];
    float* out = (float*)d_out;

    // tuple output layout: out [B*M*H] then pos_s [B*M*3]; guard against
    // a layout mismatch so we never write OOB.
    float* poss;
    if (out_size >= Bsz * Mc * (Hd + 3)) {
        poss = out + (size_t)Bsz * Mc * Hd;
    } else {
        void* tmp = nullptr;
        cudaGetSymbolAddress(&tmp, g_poss_dump);
        poss = (float*)tmp;
    }

    cudaFuncSetAttribute(mlp_kernel, cudaFuncAttributeMaxDynamicSharedMemorySize,
                         SMEM_BYTES);
    cudaFuncSetAttribute(fps_kernel, cudaFuncAttributeMaxDynamicSharedMemorySize,
                         3 * Npt * 4);

    fps_kernel<<<Bsz, FPS_T, 3 * Npt * 4>>>(pos);
    query_kernel<<<(Bsz * Mc) / QWARPS, QWARPS * 32>>>(pos, poss);
    mlp_kernel<<<152, MLP_T, SMEM_BYTES>>>(x, pos, W1, b1, W2, b2, out);
}

// round 4
// speedup vs baseline: 2.2226x; 2.1668x over previous
#include <cuda_runtime.h>
#include <float.h>
#include <stdint.h>

// Problem constants
#define Bsz 16
#define Npt 4096
#define Cft 64
#define Mc  1024
#define Kn  64
#define Hd  128
#define CIN 67   // C+3

// ---------------- scratch (device globals; no allocation allowed) --------
__device__ int   g_idx[Bsz*Mc];
__device__ int   g_nbr[Bsz*Mc*Kn];
__device__ int   g_cnt[Bsz*Mc];
__device__ float g_ctr[Bsz*Mc*3];
__device__ float g_poss_dump[Bsz*Mc*3];  // fallback if out buffer has no pos_s region

typedef unsigned long long ull;

// ---------------- f32x2 helpers ------------------------------------------
__device__ __forceinline__ ull fma2(ull a, ull b, ull c) {
    ull d;
    asm("fma.rn.f32x2 %0, %1, %2, %3;" : "=l"(d) : "l"(a), "l"(b), "l"(c));
    return d;
}
__device__ __forceinline__ ull dup2(float x) {
    ull d;
    unsigned xi = __float_as_uint(x);
    asm("mov.b64 %0, {%1, %2};" : "=l"(d) : "r"(xi), "r"(xi));
    return d;
}
__device__ __forceinline__ void unpk(ull v, float& lo, float& hi) {
    unsigned a, b;
    asm("mov.b64 {%0, %1}, %2;" : "=r"(a), "=r"(b) : "l"(v));
    lo = __uint_as_float(a);
    hi = __uint_as_float(b);
}

// ============================ 1) FPS ======================================
// (unchanged from R3 — bit-exact, 435us)
#define FPS_T 1024
#define FPPT 4

extern __shared__ float fps_sm[];

__global__ __launch_bounds__(FPS_T) void fps_kernel(const float* __restrict__ pos) {
    float* spx = fps_sm;            // 4096
    float* spy = spx + Npt;         // 4096
    float* spz = spy + Npt;         // 4096
    __shared__ unsigned swv[32];
    __shared__ int s_idx[2];

    int b = blockIdx.x;
    const float* p = pos + b * Npt * 3;
    int t = threadIdx.x;
    int lane = t & 31;
    int w = t >> 5;

    float px[FPPT], py[FPPT], pz[FPPT], dd[FPPT];
#pragma unroll
    for (int j = 0; j < FPPT; j++) {
        int i = t + j * FPS_T;
        float xx = p[i * 3 + 0];
        float yy = p[i * 3 + 1];
        float zz = p[i * 3 + 2];
        px[j] = xx; py[j] = yy; pz[j] = zz;
        spx[i] = xx; spy[i] = yy; spz[i] = zz;
        dd[j] = FLT_MAX;
    }
    if (t == 0) { g_idx[b * Mc] = 0; s_idx[0] = 0x7fffffff; s_idx[1] = 0x7fffffff; }
    __syncthreads();

    int last = 0;
    int par  = 0;
    for (int s = 1; s < Mc; s++) {
        float lx = spx[last], ly = spy[last], lz = spz[last];
        unsigned vmx = 0u;
#pragma unroll
        for (int j = 0; j < FPPT; j++) {
            float dx = __fsub_rn(px[j], lx);
            float dy = __fsub_rn(py[j], ly);
            float dz = __fsub_rn(pz[j], lz);
            float d  = __fadd_rn(__fadd_rn(__fmul_rn(dx, dx), __fmul_rn(dy, dy)),
                                 __fmul_rn(dz, dz));
            float v = fminf(dd[j], d);
            dd[j] = v;
            unsigned vu = __float_as_uint(v);
            vmx = vmx > vu ? vmx : vu;
        }
        unsigned wmax = __reduce_max_sync(0xffffffffu, vmx);
        if (lane == 0) swv[w] = wmax;
        __syncthreads();
        unsigned vm_u = __reduce_max_sync(0xffffffffu, swv[lane]);
        float vm = __uint_as_float(vm_u);
        int cand = 0x7fffffff;
#pragma unroll
        for (int j = FPPT - 1; j >= 0; j--) {
            if (dd[j] == vm) cand = t + j * FPS_T;
        }
        if (cand != 0x7fffffff) atomicMin(&s_idx[par], cand);
        if (t == 0) s_idx[par ^ 1] = 0x7fffffff;
        __syncthreads();
        last = s_idx[par];
        par ^= 1;
        if (t == 0) g_idx[b * Mc + s] = last;
    }
}

// ============================ 2) radius query =============================
// (unchanged — bit-identical membership decisions)
#define QWARPS 8

__global__ __launch_bounds__(QWARPS * 32) void query_kernel(
    const float* __restrict__ pos, float* __restrict__ poss_out) {
    int cm   = blockIdx.x * QWARPS + (threadIdx.x >> 5);
    int lane = threadIdx.x & 31;
    int b    = cm >> 10;
    const float* p = pos + b * Npt * 3;

    int   ci = g_idx[cm];
    float sx = p[ci * 3 + 0], sy = p[ci * 3 + 1], sz = p[ci * 3 + 2];
    if (lane == 0) {
        poss_out[cm * 3 + 0] = sx;
        poss_out[cm * 3 + 1] = sy;
        poss_out[cm * 3 + 2] = sz;
        g_ctr[cm * 3 + 0] = sx;
        g_ctr[cm * 3 + 1] = sy;
        g_ctr[cm * 3 + 2] = sz;
    }
    float sn = __fadd_rn(__fadd_rn(__fmul_rn(sx, sx), __fmul_rn(sy, sy)),
                         __fmul_rn(sz, sz));
    const float R2 = 0.2f * 0.2f;

    int cnt = 0;
    for (int base = 0; base < Npt; base += 32) {
        int   i = base + lane;
        float xx = p[i * 3 + 0], yy = p[i * 3 + 1], zz = p[i * 3 + 2];
        float pn = __fadd_rn(__fadd_rn(__fmul_rn(xx, xx), __fmul_rn(yy, yy)),
                             __fmul_rn(zz, zz));
        float dot = __fadd_rn(__fadd_rn(__fmul_rn(sx, xx), __fmul_rn(sy, yy)),
                              __fmul_rn(sz, zz));
        float d2 = __fsub_rn(__fadd_rn(sn, pn), __fmul_rn(2.0f, dot));
        bool  in = (d2 <= R2);
        unsigned ball = __ballot_sync(0xffffffffu, in);
        if (in) {
            int ppos = cnt + __popc(ball & ((1u << lane) - 1u));
            if (ppos < Kn) g_nbr[cm * Kn + ppos] = i;
        }
        cnt += __popc(ball);
        if (cnt >= Kn) break;
    }
    if (cnt > Kn) cnt = Kn;
    for (int k = cnt + lane; k < Kn; k += 32) g_nbr[cm * Kn + k] = 0;
    if (lane == 0) g_cnt[cm] = cnt;
}

// ============================ 3) MLP + masked max =========================
// Persistent blocks (1/SM), 256 threads, one center per iteration.
// Thread tile: 4 rows x 8 cols (16 ull f32x2 accumulators).
// KEY FIX: weights stored in smem with a 2-word pad per 32-word group
// (dst = r*136 + col + 2*(col>>5)) so the 16 col-group LDS.64 reads per
// warp hit 16 DISTINCT even bank residues -> 1 wavefront each (was 4-way
// conflicted at tx*8, which made the smem crossbar the binding pipe).
// feat/h1 row-major; A-operand loads are broadcast scalars (1 wf).
#define MLP_T 256
#define LDC 68       // feat row pitch (floats)
#define LDH 132      // h1 row pitch (floats)
#define WP  136      // padded weight row pitch (floats): 128 + 4 groups * 2

#define SMEM_FLOATS ((CIN + Hd) * WP + Hd + Hd + Kn * LDC + Kn * LDH + 16 * Hd)
#define SMEM_BYTES  (SMEM_FLOATS * 4)

extern __shared__ float smem[];

__global__ __launch_bounds__(MLP_T, 1) void mlp_kernel(
    const float* __restrict__ x, const float* __restrict__ pos,
    const float* __restrict__ W1, const float* __restrict__ b1,
    const float* __restrict__ W2, const float* __restrict__ b2,
    float* __restrict__ out) {
    float* W1s  = smem;                    // 67*136 (padded layout)
    float* W2s  = W1s + CIN * WP;          // 128*136 (padded layout)
    float* b1s  = W2s + Hd * WP;           // 128
    float* b2s  = b1s + Hd;                // 128
    float* feat = b2s + Hd;                // 64*68
    float* h1s  = feat + Kn * LDC;         // 64*132
    float* smax = h1s + Kn * LDH;          // 16*128

    int tid = threadIdx.x;
    // stage weights into padded-bank layout
    for (int i = tid; i < CIN * Hd; i += MLP_T) {
        int r = i >> 7, col = i & 127;
        W1s[r * WP + col + 2 * (col >> 5)] = W1[i];
    }
    for (int i = tid; i < Hd * Hd; i += MLP_T) {
        int r = i >> 7, col = i & 127;
        W2s[r * WP + col + 2 * (col >> 5)] = W2[i];
    }
    if (tid < Hd) { b1s[tid] = b1[tid]; b2s[tid] = b2[tid]; }

    int ty   = tid >> 4;           // 0..15 -> 4 rows each
    int tx   = tid & 15;           // 0..15 -> 8 cols each
    int row0 = ty * 4;
    int col0 = tx * 8;
    int wcol = col0 + 2 * (col0 >> 5);   // padded offset, distinct banks

    for (int cm = blockIdx.x; cm < Bsz * Mc; cm += gridDim.x) {
        int b = cm >> 10;
        __syncthreads();  // weights ready (1st iter) / feat,h1,smax reusable

        // gather x features -> feat[k][c], nbr indices read straight from gmem
        const float* xb  = x + (size_t)b * Npt * Cft;
        const int*   nbp = g_nbr + cm * Kn;
#pragma unroll
        for (int j = tid; j < Kn * 16; j += MLP_T) {
            int k  = j >> 4;
            int c4 = (j & 15) << 2;
            int nb = __ldg(nbp + k);
            float4 v = *(const float4*)(xb + (size_t)nb * Cft + c4);
            *(float4*)(feat + k * LDC + c4) = v;
        }
        if (tid < Kn) {
            float cx = g_ctr[cm * 3 + 0], cy = g_ctr[cm * 3 + 1], cz = g_ctr[cm * 3 + 2];
            const float* pb = pos + b * Npt * 3;
            int n3 = __ldg(nbp + tid) * 3;
            feat[tid * LDC + 64] = pb[n3 + 0] - cx;
            feat[tid * LDC + 65] = pb[n3 + 1] - cy;
            feat[tid * LDC + 66] = pb[n3 + 2] - cz;
        }
        int cnt = __ldg(g_cnt + cm);
        __syncthreads();

        ull acc[4][4];
#pragma unroll
        for (int r = 0; r < 4; r++)
#pragma unroll
            for (int q = 0; q < 4; q++) acc[r][q] = 0ULL;

        // -------- layer 1: feat[64x67] @ W1[67x128] ----------
        {
            const float* a0 = feat + row0 * LDC;
            const float* wp = W1s + wcol;
#pragma unroll 4
            for (int c = 0; c < CIN; c++) {
                ull w0 = *(const ull*)(wp + 0);
                ull w1 = *(const ull*)(wp + 2);
                ull w2 = *(const ull*)(wp + 4);
                ull w3 = *(const ull*)(wp + 6);
                wp += WP;
                ull da0 = dup2(a0[c]);
                ull da1 = dup2(a0[LDC + c]);
                ull da2 = dup2(a0[2 * LDC + c]);
                ull da3 = dup2(a0[3 * LDC + c]);
                acc[0][0] = fma2(da0, w0, acc[0][0]); acc[0][1] = fma2(da0, w1, acc[0][1]);
                acc[0][2] = fma2(da0, w2, acc[0][2]); acc[0][3] = fma2(da0, w3, acc[0][3]);
                acc[1][0] = fma2(da1, w0, acc[1][0]); acc[1][1] = fma2(da1, w1, acc[1][1]);
                acc[1][2] = fma2(da1, w2, acc[1][2]); acc[1][3] = fma2(da1, w3, acc[1][3]);
                acc[2][0] = fma2(da2, w0, acc[2][0]); acc[2][1] = fma2(da2, w1, acc[2][1]);
                acc[2][2] = fma2(da2, w2, acc[2][2]); acc[2][3] = fma2(da2, w3, acc[2][3]);
                acc[3][0] = fma2(da3, w0, acc[3][0]); acc[3][1] = fma2(da3, w1, acc[3][1]);
                acc[3][2] = fma2(da3, w2, acc[3][2]); acc[3][3] = fma2(da3, w3, acc[3][3]);
            }
        }
        // bias + relu + store h1 rows (produced & consumed within this warp)
#pragma unroll
        for (int r = 0; r < 4; r++) {
            float f[8];
#pragma unroll
            for (int q = 0; q < 4; q++) unpk(acc[r][q], f[2 * q], f[2 * q + 1]);
            float* hrow = h1s + (row0 + r) * LDH + col0;
            float4 v0, v1;
            v0.x = fmaxf(f[0] + b1s[col0 + 0], 0.f);
            v0.y = fmaxf(f[1] + b1s[col0 + 1], 0.f);
            v0.z = fmaxf(f[2] + b1s[col0 + 2], 0.f);
            v0.w = fmaxf(f[3] + b1s[col0 + 3], 0.f);
            v1.x = fmaxf(f[4] + b1s[col0 + 4], 0.f);
            v1.y = fmaxf(f[5] + b1s[col0 + 5], 0.f);
            v1.z = fmaxf(f[6] + b1s[col0 + 6], 0.f);
            v1.w = fmaxf(f[7] + b1s[col0 + 7], 0.f);
            *(float4*)(hrow)     = v0;
            *(float4*)(hrow + 4) = v1;
        }
        __syncwarp();

        // -------- layer 2: h1[64x128] @ W2[128x128] ----------
#pragma unroll
        for (int r = 0; r < 4; r++)
#pragma unroll
            for (int q = 0; q < 4; q++) acc[r][q] = 0ULL;
        {
            const float* a0 = h1s + row0 * LDH;
            const float* wp = W2s + wcol;
#pragma unroll 4
            for (int h = 0; h < Hd; h++) {
                ull w0 = *(const ull*)(wp + 0);
                ull w1 = *(const ull*)(wp + 2);
                ull w2 = *(const ull*)(wp + 4);
                ull w3 = *(const ull*)(wp + 6);
                wp += WP;
                ull da0 = dup2(a0[h]);
                ull da1 = dup2(a0[LDH + h]);
                ull da2 = dup2(a0[2 * LDH + h]);
                ull da3 = dup2(a0[3 * LDH + h]);
                acc[0][0] = fma2(da0, w0, acc[0][0]); acc[0][1] = fma2(da0, w1, acc[0][1]);
                acc[0][2] = fma2(da0, w2, acc[0][2]); acc[0][3] = fma2(da0, w3, acc[0][3]);
                acc[1][0] = fma2(da1, w0, acc[1][0]); acc[1][1] = fma2(da1, w1, acc[1][1]);
                acc[1][2] = fma2(da1, w2, acc[1][2]); acc[1][3] = fma2(da1, w3, acc[1][3]);
                acc[2][0] = fma2(da2, w0, acc[2][0]); acc[2][1] = fma2(da2, w1, acc[2][1]);
                acc[2][2] = fma2(da2, w2, acc[2][2]); acc[2][3] = fma2(da2, w3, acc[2][3]);
                acc[3][0] = fma2(da3, w0, acc[3][0]); acc[3][1] = fma2(da3, w1, acc[3][1]);
                acc[3][2] = fma2(da3, w2, acc[3][2]); acc[3][3] = fma2(da3, w3, acc[3][3]);
            }
        }

        // -------- bias + relu + masked max (mask only here) --------------
        float cmax[8];
#pragma unroll
        for (int q = 0; q < 8; q++) cmax[q] = -1e30f;
        int rmax = cnt - row0;
        if (rmax > 4) rmax = 4;
        for (int r = 0; r < rmax; r++) {
            float f[8];
#pragma unroll
            for (int q = 0; q < 4; q++) unpk(acc[r][q], f[2 * q], f[2 * q + 1]);
#pragma unroll
            for (int q = 0; q < 8; q++) {
                float hv = fmaxf(f[q] + b2s[col0 + q], 0.f);
                cmax[q]  = fmaxf(cmax[q], hv);
            }
        }
        {
            float4 v0, v1;
            v0.x = cmax[0]; v0.y = cmax[1]; v0.z = cmax[2]; v0.w = cmax[3];
            v1.x = cmax[4]; v1.y = cmax[5]; v1.z = cmax[6]; v1.w = cmax[7];
            *(float4*)(smax + ty * Hd + col0)     = v0;
            *(float4*)(smax + ty * Hd + col0 + 4) = v1;
        }
        __syncthreads();
        if (tid < Hd) {
            float mv = -1e30f;
#pragma unroll
            for (int yy = 0; yy < 16; yy++) mv = fmaxf(mv, smax[yy * Hd + tid]);
            out[(size_t)cm * Hd + tid] = (cnt > 0) ? mv : 0.0f;
        }
    }
}

// ============================ launch ======================================
extern "C" void kernel_launch(void* const* d_in, const int* in_sizes, int n_in,
                              void* d_out, int out_size) {
    const float* x   = (const float*)d_in[0];
    const float* pos = (const float*)d_in[1];
    const float* W1  = (const float*)d_in[2];
    const float* b1  = (const float*)d_in[3];
    const float* W2  = (const float*)d_in[4];
    const float* b2  = (const float*)d_in[5];
    float* out = (float*)d_out;

    float* poss;
    if (out_size >= Bsz * Mc * (Hd + 3)) {
        poss = out + (size_t)Bsz * Mc * Hd;
    } else {
        void* tmp = nullptr;
        cudaGetSymbolAddress(&tmp, g_poss_dump);
        poss = (float*)tmp;
    }

    cudaFuncSetAttribute(mlp_kernel, cudaFuncAttributeMaxDynamicSharedMemorySize,
                         SMEM_BYTES);
    cudaFuncSetAttribute(fps_kernel, cudaFuncAttributeMaxDynamicSharedMemorySize,
                         3 * Npt * 4);

    fps_kernel<<<Bsz, FPS_T, 3 * Npt * 4>>>(pos);
    query_kernel<<<(Bsz * Mc) / QWARPS, QWARPS * 32>>>(pos, poss);
    mlp_kernel<<<152, MLP_T, SMEM_BYTES>>>(x, pos, W1, b1, W2, b2, out);
}

// round 5
// speedup vs baseline: 2.3597x; 1.0617x over previous
#include <cuda_runtime.h>
#include <float.h>
#include <stdint.h>

// Problem constants
#define Bsz 16
#define Npt 4096
#define Cft 64
#define Mc  1024
#define Kn  64
#define Hd  128
#define CIN 67   // C+3

// ---------------- scratch (device globals; no allocation allowed) --------
__device__ int   g_idx[Bsz*Mc];
__device__ int   g_nbr[Bsz*Mc*Kn];
__device__ int   g_cnt[Bsz*Mc];
__device__ float g_ctr[Bsz*Mc*3];
__device__ float g_poss_dump[Bsz*Mc*3];  // fallback if out buffer has no pos_s region

typedef unsigned long long ull;

// ---------------- f32x2 helpers ------------------------------------------
__device__ __forceinline__ ull fma2(ull a, ull b, ull c) {
    ull d;
    asm("fma.rn.f32x2 %0, %1, %2, %3;" : "=l"(d) : "l"(a), "l"(b), "l"(c));
    return d;
}
__device__ __forceinline__ ull dup2(float x) {
    ull d;
    unsigned xi = __float_as_uint(x);
    asm("mov.b64 %0, {%1, %2};" : "=l"(d) : "r"(xi), "r"(xi));
    return d;
}
__device__ __forceinline__ void unpk(ull v, float& lo, float& hi) {
    unsigned a, b;
    asm("mov.b64 {%0, %1}, %2;" : "=r"(a), "=r"(b) : "l"(v));
    lo = __uint_as_float(a);
    hi = __uint_as_float(b);
}

// ============================ 1) FPS ======================================
// One block per batch, 1024 threads, 4 points/thread in registers.
// ONE barrier per step: per-warp (max-value, min-index) via REDUX pairs into
// parity-double-buffered smem; after the barrier every warp redundantly
// reduces the 32 pairs (2 REDUX) -> all threads get `last` directly.
// Distance arithmetic byte-identical to R4 (picks cannot change).
// Tie-break: max value, then min global index == jnp.argmax first-occurrence.
#define FPS_T 1024
#define FPPT 4

extern __shared__ float fps_sm[];

__global__ __launch_bounds__(FPS_T) void fps_kernel(const float* __restrict__ pos) {
    float* spx = fps_sm;            // 4096
    float* spy = spx + Npt;         // 4096
    float* spz = spy + Npt;         // 4096
    __shared__ unsigned swv[2][32];
    __shared__ unsigned swc[2][32];

    int b = blockIdx.x;
    const float* p = pos + b * Npt * 3;
    int t = threadIdx.x;
    int lane = t & 31;
    int w = t >> 5;

    float px[FPPT], py[FPPT], pz[FPPT], dd[FPPT];
#pragma unroll
    for (int j = 0; j < FPPT; j++) {
        int i = t + j * FPS_T;
        float xx = p[i * 3 + 0];
        float yy = p[i * 3 + 1];
        float zz = p[i * 3 + 2];
        px[j] = xx; py[j] = yy; pz[j] = zz;
        spx[i] = xx; spy[i] = yy; spz[i] = zz;
        dd[j] = FLT_MAX;
    }
    if (t == 0) g_idx[b * Mc] = 0;
    __syncthreads();

    int last = 0;
    int par  = 0;
    for (int s = 1; s < Mc; s++) {
        float lx = spx[last], ly = spy[last], lz = spz[last];
        unsigned vmx = 0u;
#pragma unroll
        for (int j = 0; j < FPPT; j++) {
            float dx = __fsub_rn(px[j], lx);
            float dy = __fsub_rn(py[j], ly);
            float dz = __fsub_rn(pz[j], lz);
            float d  = __fadd_rn(__fadd_rn(__fmul_rn(dx, dx), __fmul_rn(dy, dy)),
                                 __fmul_rn(dz, dz));
            float v = fminf(dd[j], d);
            dd[j] = v;
            unsigned vu = __float_as_uint(v);
            vmx = vmx > vu ? vmx : vu;
        }
        // thread-local first index achieving vmx
        unsigned cand = 0x7fffffffu;
#pragma unroll
        for (int j = FPPT - 1; j >= 0; j--) {
            if (__float_as_uint(dd[j]) == vmx) cand = (unsigned)(t + j * FPS_T);
        }
        // warp (max value, min index) via two REDUX
        unsigned wmax = __reduce_max_sync(0xffffffffu, vmx);
        unsigned csel = (vmx == wmax) ? cand : 0x7fffffffu;
        unsigned wcnd = __reduce_min_sync(0xffffffffu, csel);
        if (lane == 0) { swv[par][w] = wmax; swc[par][w] = wcnd; }
        __syncthreads();
        // every warp reduces the 32 warp pairs redundantly
        unsigned vv = swv[par][lane];
        unsigned cc = swc[par][lane];
        unsigned vm = __reduce_max_sync(0xffffffffu, vv);
        unsigned cm = __reduce_min_sync(0xffffffffu, (vv == vm) ? cc : 0x7fffffffu);
        last = (int)cm;
        par ^= 1;
        if (t == 0) g_idx[b * Mc + s] = last;
    }
}

// ============================ 2) radius query =============================
// (unchanged — bit-identical membership decisions)
#define QWARPS 8

__global__ __launch_bounds__(QWARPS * 32) void query_kernel(
    const float* __restrict__ pos, float* __restrict__ poss_out) {
    int cm   = blockIdx.x * QWARPS + (threadIdx.x >> 5);
    int lane = threadIdx.x & 31;
    int b    = cm >> 10;
    const float* p = pos + b * Npt * 3;

    int   ci = g_idx[cm];
    float sx = p[ci * 3 + 0], sy = p[ci * 3 + 1], sz = p[ci * 3 + 2];
    if (lane == 0) {
        poss_out[cm * 3 + 0] = sx;
        poss_out[cm * 3 + 1] = sy;
        poss_out[cm * 3 + 2] = sz;
        g_ctr[cm * 3 + 0] = sx;
        g_ctr[cm * 3 + 1] = sy;
        g_ctr[cm * 3 + 2] = sz;
    }
    float sn = __fadd_rn(__fadd_rn(__fmul_rn(sx, sx), __fmul_rn(sy, sy)),
                         __fmul_rn(sz, sz));
    const float R2 = 0.2f * 0.2f;

    int cnt = 0;
    for (int base = 0; base < Npt; base += 32) {
        int   i = base + lane;
        float xx = p[i * 3 + 0], yy = p[i * 3 + 1], zz = p[i * 3 + 2];
        float pn = __fadd_rn(__fadd_rn(__fmul_rn(xx, xx), __fmul_rn(yy, yy)),
                             __fmul_rn(zz, zz));
        float dot = __fadd_rn(__fadd_rn(__fmul_rn(sx, xx), __fmul_rn(sy, yy)),
                              __fmul_rn(sz, zz));
        float d2 = __fsub_rn(__fadd_rn(sn, pn), __fmul_rn(2.0f, dot));
        bool  in = (d2 <= R2);
        unsigned ball = __ballot_sync(0xffffffffu, in);
        if (in) {
            int ppos = cnt + __popc(ball & ((1u << lane) - 1u));
            if (ppos < Kn) g_nbr[cm * Kn + ppos] = i;
        }
        cnt += __popc(ball);
        if (cnt >= Kn) break;
    }
    if (cnt > Kn) cnt = Kn;
    for (int k = cnt + lane; k < Kn; k += 32) g_nbr[cm * Kn + k] = 0;
    if (lane == 0) g_cnt[cm] = cnt;
}

// ============================ 3) MLP + masked max =========================
// Persistent blocks (1/SM), 512 threads = 2 teams x 256, one center per team
// per iteration (4 warps/SMSP to hide LDS/FMA latency).
// Thread tile: 4 rows x 8 cols (16 ull f32x2 accumulators).
// Weights in bank-padded smem layout (dst = r*136 + col + 2*(col>>5)) so
// the 16 col-group LDS.64 reads per warp hit 16 distinct even banks.
#define MLP_T 512
#define TEAM_T 256
#define LDC 68       // feat row pitch (floats)
#define LDH 132      // h1 row pitch (floats)
#define WP  136      // padded weight row pitch (floats): 128 + 4 groups * 2

#define SMEM_FLOATS ((CIN + Hd) * WP + Hd + Hd + 2 * (Kn * LDC + Kn * LDH + 16 * Hd))
#define SMEM_BYTES  (SMEM_FLOATS * 4)

extern __shared__ float smem[];

__global__ __launch_bounds__(MLP_T, 1) void mlp_kernel(
    const float* __restrict__ x, const float* __restrict__ pos,
    const float* __restrict__ W1, const float* __restrict__ b1,
    const float* __restrict__ W2, const float* __restrict__ b2,
    float* __restrict__ out) {
    float* W1s   = smem;                        // 67*136 (padded)
    float* W2s   = W1s + CIN * WP;              // 128*136 (padded)
    float* b1s   = W2s + Hd * WP;               // 128
    float* b2s   = b1s + Hd;                    // 128
    float* featb = b2s + Hd;                    // 2 * 64*68
    float* h1b   = featb + 2 * Kn * LDC;        // 2 * 64*132
    float* smaxb = h1b + 2 * Kn * LDH;          // 2 * 16*128

    int tid = threadIdx.x;
    // stage weights into padded-bank layout
    for (int i = tid; i < CIN * Hd; i += MLP_T) {
        int r = i >> 7, col = i & 127;
        W1s[r * WP + col + 2 * (col >> 5)] = W1[i];
    }
    for (int i = tid; i < Hd * Hd; i += MLP_T) {
        int r = i >> 7, col = i & 127;
        W2s[r * WP + col + 2 * (col >> 5)] = W2[i];
    }
    if (tid < Hd) { b1s[tid] = b1[tid]; b2s[tid] = b2[tid]; }

    int team = tid >> 8;            // 0/1
    int ttid = tid & 255;
    int ty   = ttid >> 4;           // 0..15 -> 4 rows each
    int tx   = ttid & 15;           // 0..15 -> 8 cols each
    int row0 = ty * 4;
    int col0 = tx * 8;
    int wcol = col0 + 2 * (col0 >> 5);   // padded offset, distinct banks

    float* feat = featb + team * Kn * LDC;
    float* h1s  = h1b   + team * Kn * LDH;
    float* smax = smaxb + team * 16 * Hd;

    for (int base = blockIdx.x * 2; base < Bsz * Mc; base += gridDim.x * 2) {
        int cm = base + team;
        int b  = cm >> 10;
        __syncthreads();  // weights ready (1st iter) / feat,h1,smax reusable

        // gather x features -> feat[k][c]
        const float* xb  = x + (size_t)b * Npt * Cft;
        const int*   nbp = g_nbr + cm * Kn;
#pragma unroll
        for (int j = ttid; j < Kn * 16; j += TEAM_T) {
            int k  = j >> 4;
            int c4 = (j & 15) << 2;
            int nb = __ldg(nbp + k);
            float4 v = *(const float4*)(xb + (size_t)nb * Cft + c4);
            *(float4*)(feat + k * LDC + c4) = v;
        }
        if (ttid < Kn) {
            float cx = g_ctr[cm * 3 + 0], cy = g_ctr[cm * 3 + 1], cz = g_ctr[cm * 3 + 2];
            const float* pb = pos + b * Npt * 3;
            int n3 = __ldg(nbp + ttid) * 3;
            feat[ttid * LDC + 64] = pb[n3 + 0] - cx;
            feat[ttid * LDC + 65] = pb[n3 + 1] - cy;
            feat[ttid * LDC + 66] = pb[n3 + 2] - cz;
        }
        int cnt = __ldg(g_cnt + cm);
        __syncthreads();

        ull acc[4][4];
#pragma unroll
        for (int r = 0; r < 4; r++)
#pragma unroll
            for (int q = 0; q < 4; q++) acc[r][q] = 0ULL;

        // -------- layer 1: feat[64x67] @ W1[67x128] ----------
        {
            const float* a0 = feat + row0 * LDC;
            const float* wp = W1s + wcol;
#pragma unroll 4
            for (int c = 0; c < CIN; c++) {
                ull w0 = *(const ull*)(wp + 0);
                ull w1 = *(const ull*)(wp + 2);
                ull w2 = *(const ull*)(wp + 4);
                ull w3 = *(const ull*)(wp + 6);
                wp += WP;
                ull da0 = dup2(a0[c]);
                ull da1 = dup2(a0[LDC + c]);
                ull da2 = dup2(a0[2 * LDC + c]);
                ull da3 = dup2(a0[3 * LDC + c]);
                acc[0][0] = fma2(da0, w0, acc[0][0]); acc[0][1] = fma2(da0, w1, acc[0][1]);
                acc[0][2] = fma2(da0, w2, acc[0][2]); acc[0][3] = fma2(da0, w3, acc[0][3]);
                acc[1][0] = fma2(da1, w0, acc[1][0]); acc[1][1] = fma2(da1, w1, acc[1][1]);
                acc[1][2] = fma2(da1, w2, acc[1][2]); acc[1][3] = fma2(da1, w3, acc[1][3]);
                acc[2][0] = fma2(da2, w0, acc[2][0]); acc[2][1] = fma2(da2, w1, acc[2][1]);
                acc[2][2] = fma2(da2, w2, acc[2][2]); acc[2][3] = fma2(da2, w3, acc[2][3]);
                acc[3][0] = fma2(da3, w0, acc[3][0]); acc[3][1] = fma2(da3, w1, acc[3][1]);
                acc[3][2] = fma2(da3, w2, acc[3][2]); acc[3][3] = fma2(da3, w3, acc[3][3]);
            }
        }
        // bias + relu + store h1 rows (produced & consumed within this warp)
#pragma unroll
        for (int r = 0; r < 4; r++) {
            float f[8];
#pragma unroll
            for (int q = 0; q < 4; q++) unpk(acc[r][q], f[2 * q], f[2 * q + 1]);
            float* hrow = h1s + (row0 + r) * LDH + col0;
            float4 v0, v1;
            v0.x = fmaxf(f[0] + b1s[col0 + 0], 0.f);
            v0.y = fmaxf(f[1] + b1s[col0 + 1], 0.f);
            v0.z = fmaxf(f[2] + b1s[col0 + 2], 0.f);
            v0.w = fmaxf(f[3] + b1s[col0 + 3], 0.f);
            v1.x = fmaxf(f[4] + b1s[col0 + 4], 0.f);
            v1.y = fmaxf(f[5] + b1s[col0 + 5], 0.f);
            v1.z = fmaxf(f[6] + b1s[col0 + 6], 0.f);
            v1.w = fmaxf(f[7] + b1s[col0 + 7], 0.f);
            *(float4*)(hrow)     = v0;
            *(float4*)(hrow + 4) = v1;
        }
        __syncwarp();

        // -------- layer 2: h1[64x128] @ W2[128x128] ----------
#pragma unroll
        for (int r = 0; r < 4; r++)
#pragma unroll
            for (int q = 0; q < 4; q++) acc[r][q] = 0ULL;
        {
            const float* a0 = h1s + row0 * LDH;
            const float* wp = W2s + wcol;
#pragma unroll 4
            for (int h = 0; h < Hd; h++) {
                ull w0 = *(const ull*)(wp + 0);
                ull w1 = *(const ull*)(wp + 2);
                ull w2 = *(const ull*)(wp + 4);
                ull w3 = *(const ull*)(wp + 6);
                wp += WP;
                ull da0 = dup2(a0[h]);
                ull da1 = dup2(a0[LDH + h]);
                ull da2 = dup2(a0[2 * LDH + h]);
                ull da3 = dup2(a0[3 * LDH + h]);
                acc[0][0] = fma2(da0, w0, acc[0][0]); acc[0][1] = fma2(da0, w1, acc[0][1]);
                acc[0][2] = fma2(da0, w2, acc[0][2]); acc[0][3] = fma2(da0, w3, acc[0][3]);
                acc[1][0] = fma2(da1, w0, acc[1][0]); acc[1][1] = fma2(da1, w1, acc[1][1]);
                acc[1][2] = fma2(da1, w2, acc[1][2]); acc[1][3] = fma2(da1, w3, acc[1][3]);
                acc[2][0] = fma2(da2, w0, acc[2][0]); acc[2][1] = fma2(da2, w1, acc[2][1]);
                acc[2][2] = fma2(da2, w2, acc[2][2]); acc[2][3] = fma2(da2, w3, acc[2][3]);
                acc[3][0] = fma2(da3, w0, acc[3][0]); acc[3][1] = fma2(da3, w1, acc[3][1]);
                acc[3][2] = fma2(da3, w2, acc[3][2]); acc[3][3] = fma2(da3, w3, acc[3][3]);
            }
        }

        // -------- bias + relu + masked max (mask only here) --------------
        float cmax[8];
#pragma unroll
        for (int q = 0; q < 8; q++) cmax[q] = -1e30f;
        int rmax = cnt - row0;
        if (rmax > 4) rmax = 4;
        for (int r = 0; r < rmax; r++) {
            float f[8];
#pragma unroll
            for (int q = 0; q < 4; q++) unpk(acc[r][q], f[2 * q], f[2 * q + 1]);
#pragma unroll
            for (int q = 0; q < 8; q++) {
                float hv = fmaxf(f[q] + b2s[col0 + q], 0.f);
                cmax[q]  = fmaxf(cmax[q], hv);
            }
        }
        {
            float4 v0, v1;
            v0.x = cmax[0]; v0.y = cmax[1]; v0.z = cmax[2]; v0.w = cmax[3];
            v1.x = cmax[4]; v1.y = cmax[5]; v1.z = cmax[6]; v1.w = cmax[7];
            *(float4*)(smax + ty * Hd + col0)     = v0;
            *(float4*)(smax + ty * Hd + col0 + 4) = v1;
        }
        __syncthreads();
        if (ttid < Hd) {
            float mv = -1e30f;
#pragma unroll
            for (int yy = 0; yy < 16; yy++) mv = fmaxf(mv, smax[yy * Hd + ttid]);
            out[(size_t)cm * Hd + ttid] = (cnt > 0) ? mv : 0.0f;
        }
    }
}

// ============================ launch ======================================
extern "C" void kernel_launch(void* const* d_in, const int* in_sizes, int n_in,
                              void* d_out, int out_size) {
    const float* x   = (const float*)d_in[0];
    const float* pos = (const float*)d_in[1];
    const float* W1  = (const float*)d_in[2];
    const float* b1  = (const float*)d_in[3];
    const float* W2  = (const float*)d_in[4];
    const float* b2  = (const float*)d_in[5];
    float* out = (float*)d_out;

    float* poss;
    if (out_size >= Bsz * Mc * (Hd + 3)) {
        poss = out + (size_t)Bsz * Mc * Hd;
    } else {
        void* tmp = nullptr;
        cudaGetSymbolAddress(&tmp, g_poss_dump);
        poss = (float*)tmp;
    }

    cudaFuncSetAttribute(mlp_kernel, cudaFuncAttributeMaxDynamicSharedMemorySize,
                         SMEM_BYTES);
    cudaFuncSetAttribute(fps_kernel, cudaFuncAttributeMaxDynamicSharedMemorySize,
                         3 * Npt * 4);

    fps_kernel<<<Bsz, FPS_T, 3 * Npt * 4>>>(pos);
    query_kernel<<<(Bsz * Mc) / QWARPS, QWARPS * 32>>>(pos, poss);
    mlp_kernel<<<152, MLP_T, SMEM_BYTES>>>(x, pos, W1, b1, W2, b2, out);
}

// round 6
// speedup vs baseline: 2.3711x; 1.0048x over previous
#include <cuda_runtime.h>
#include <float.h>
#include <stdint.h>

// Problem constants
#define Bsz 16
#define Npt 4096
#define Cft 64
#define Mc  1024
#define Kn  64
#define Hd  128
#define CIN 67   // C+3

// ---------------- scratch (device globals; no allocation allowed) --------
__device__ int   g_idx[Bsz*Mc];
__device__ int   g_nbr[Bsz*Mc*Kn];
__device__ int   g_cnt[Bsz*Mc];
__device__ float g_ctr[Bsz*Mc*3];
__device__ float g_poss_dump[Bsz*Mc*3];  // fallback if out buffer has no pos_s region

typedef unsigned long long ull;

// ---------------- f32x2 helpers ------------------------------------------
__device__ __forceinline__ ull fma2(ull a, ull b, ull c) {
    ull d;
    asm("fma.rn.f32x2 %0, %1, %2, %3;" : "=l"(d) : "l"(a), "l"(b), "l"(c));
    return d;
}
__device__ __forceinline__ ull dup2(float x) {
    ull d;
    unsigned xi = __float_as_uint(x);
    asm("mov.b64 %0, {%1, %2};" : "=l"(d) : "r"(xi), "r"(xi));
    return d;
}
__device__ __forceinline__ void unpk(ull v, float& lo, float& hi) {
    unsigned a, b;
    asm("mov.b64 {%0, %1}, %2;" : "=r"(a), "=r"(b) : "l"(v));
    lo = __uint_as_float(a);
    hi = __uint_as_float(b);
}

// ============================ 1) FPS ======================================
// One block per batch, 1024 threads, 4 points/thread in registers.
// ONE barrier per step: per-warp (max-value, min-index) via REDUX pairs into
// parity-double-buffered smem; after the barrier every warp redundantly
// reduces the 32 pairs (2 REDUX) -> all threads get `last` directly.
// Distance arithmetic byte-identical to R4 (picks cannot change).
// Tie-break: max value, then min global index == jnp.argmax first-occurrence.
#define FPS_T 1024
#define FPPT 4

extern __shared__ float fps_sm[];

__global__ __launch_bounds__(FPS_T) void fps_kernel(const float* __restrict__ pos) {
    float* spx = fps_sm;            // 4096
    float* spy = spx + Npt;         // 4096
    float* spz = spy + Npt;         // 4096
    __shared__ unsigned swv[2][32];
    __shared__ unsigned swc[2][32];

    int b = blockIdx.x;
    const float* p = pos + b * Npt * 3;
    int t = threadIdx.x;
    int lane = t & 31;
    int w = t >> 5;

    float px[FPPT], py[FPPT], pz[FPPT], dd[FPPT];
#pragma unroll
    for (int j = 0; j < FPPT; j++) {
        int i = t + j * FPS_T;
        float xx = p[i * 3 + 0];
        float yy = p[i * 3 + 1];
        float zz = p[i * 3 + 2];
        px[j] = xx; py[j] = yy; pz[j] = zz;
        spx[i] = xx; spy[i] = yy; spz[i] = zz;
        dd[j] = FLT_MAX;
    }
    if (t == 0) g_idx[b * Mc] = 0;
    __syncthreads();

    int last = 0;
    int par  = 0;
    for (int s = 1; s < Mc; s++) {
        float lx = spx[last], ly = spy[last], lz = spz[last];
        unsigned vmx = 0u;
#pragma unroll
        for (int j = 0; j < FPPT; j++) {
            float dx = __fsub_rn(px[j], lx);
            float dy = __fsub_rn(py[j], ly);
            float dz = __fsub_rn(pz[j], lz);
            float d  = __fadd_rn(__fadd_rn(__fmul_rn(dx, dx), __fmul_rn(dy, dy)),
                                 __fmul_rn(dz, dz));
            float v = fminf(dd[j], d);
            dd[j] = v;
            unsigned vu = __float_as_uint(v);
            vmx = vmx > vu ? vmx : vu;
        }
        // thread-local first index achieving vmx
        unsigned cand = 0x7fffffffu;
#pragma unroll
        for (int j = FPPT - 1; j >= 0; j--) {
            if (__float_as_uint(dd[j]) == vmx) cand = (unsigned)(t + j * FPS_T);
        }
        // warp (max value, min index) via two REDUX
        unsigned wmax = __reduce_max_sync(0xffffffffu, vmx);
        unsigned csel = (vmx == wmax) ? cand : 0x7fffffffu;
        unsigned wcnd = __reduce_min_sync(0xffffffffu, csel);
        if (lane == 0) { swv[par][w] = wmax; swc[par][w] = wcnd; }
        __syncthreads();
        // every warp reduces the 32 warp pairs redundantly
        unsigned vv = swv[par][lane];
        unsigned cc = swc[par][lane];
        unsigned vm = __reduce_max_sync(0xffffffffu, vv);
        unsigned cm = __reduce_min_sync(0xffffffffu, (vv == vm) ? cc : 0x7fffffffu);
        last = (int)cm;
        par ^= 1;
        if (t == 0) g_idx[b * Mc + s] = last;
    }
}

// ============================ 2) radius query =============================
// (unchanged — bit-identical membership decisions)
#define QWARPS 8

__global__ __launch_bounds__(QWARPS * 32) void query_kernel(
    const float* __restrict__ pos, float* __restrict__ poss_out) {
    int cm   = blockIdx.x * QWARPS + (threadIdx.x >> 5);
    int lane = threadIdx.x & 31;
    int b    = cm >> 10;
    const float* p = pos + b * Npt * 3;

    int   ci = g_idx[cm];
    float sx = p[ci * 3 + 0], sy = p[ci * 3 + 1], sz = p[ci * 3 + 2];
    if (lane == 0) {
        poss_out[cm * 3 + 0] = sx;
        poss_out[cm * 3 + 1] = sy;
        poss_out[cm * 3 + 2] = sz;
        g_ctr[cm * 3 + 0] = sx;
        g_ctr[cm * 3 + 1] = sy;
        g_ctr[cm * 3 + 2] = sz;
    }
    float sn = __fadd_rn(__fadd_rn(__fmul_rn(sx, sx), __fmul_rn(sy, sy)),
                         __fmul_rn(sz, sz));
    const float R2 = 0.2f * 0.2f;

    int cnt = 0;
    for (int base = 0; base < Npt; base += 32) {
        int   i = base + lane;
        float xx = p[i * 3 + 0], yy = p[i * 3 + 1], zz = p[i * 3 + 2];
        float pn = __fadd_rn(__fadd_rn(__fmul_rn(xx, xx), __fmul_rn(yy, yy)),
                             __fmul_rn(zz, zz));
        float dot = __fadd_rn(__fadd_rn(__fmul_rn(sx, xx), __fmul_rn(sy, yy)),
                              __fmul_rn(sz, zz));
        float d2 = __fsub_rn(__fadd_rn(sn, pn), __fmul_rn(2.0f, dot));
        bool  in = (d2 <= R2);
        unsigned ball = __ballot_sync(0xffffffffu, in);
        if (in) {
            int ppos = cnt + __popc(ball & ((1u << lane) - 1u));
            if (ppos < Kn) g_nbr[cm * Kn + ppos] = i;
        }
        cnt += __popc(ball);
        if (cnt >= Kn) break;
    }
    if (cnt > Kn) cnt = Kn;
    for (int k = cnt + lane; k < Kn; k += 32) g_nbr[cm * Kn + k] = 0;
    if (lane == 0) g_cnt[cm] = cnt;
}

// ============================ 3) MLP + masked max =========================
// Persistent blocks (1/SM), 512 threads = 2 teams x 256, one center per team
// per iteration (4 warps/SMSP to hide LDS/FMA latency).
// Thread tile: 4 rows x 8 cols (16 ull f32x2 accumulators).
// Weights in bank-padded smem layout (dst = r*136 + col + 2*(col>>5)) so
// the 16 col-group LDS.64 reads per warp hit 16 distinct even banks.
#define MLP_T 512
#define TEAM_T 256
#define LDC 68       // feat row pitch (floats)
#define LDH 132      // h1 row pitch (floats)
#define WP  136      // padded weight row pitch (floats): 128 + 4 groups * 2

#define SMEM_FLOATS ((CIN + Hd) * WP + Hd + Hd + 2 * (Kn * LDC + Kn * LDH + 16 * Hd))
#define SMEM_BYTES  (SMEM_FLOATS * 4)

extern __shared__ float smem[];

__global__ __launch_bounds__(MLP_T, 1) void mlp_kernel(
    const float* __restrict__ x, const float* __restrict__ pos,
    const float* __restrict__ W1, const float* __restrict__ b1,
    const float* __restrict__ W2, const float* __restrict__ b2,
    float* __restrict__ out) {
    float* W1s   = smem;                        // 67*136 (padded)
    float* W2s   = W1s + CIN * WP;              // 128*136 (padded)
    float* b1s   = W2s + Hd * WP;               // 128
    float* b2s   = b1s + Hd;                    // 128
    float* featb = b2s + Hd;                    // 2 * 64*68
    float* h1b   = featb + 2 * Kn * LDC;        // 2 * 64*132
    float* smaxb = h1b + 2 * Kn * LDH;          // 2 * 16*128

    int tid = threadIdx.x;
    // stage weights into padded-bank layout
    for (int i = tid; i < CIN * Hd; i += MLP_T) {
        int r = i >> 7, col = i & 127;
        W1s[r * WP + col + 2 * (col >> 5)] = W1[i];
    }
    for (int i = tid; i < Hd * Hd; i += MLP_T) {
        int r = i >> 7, col = i & 127;
        W2s[r * WP + col + 2 * (col >> 5)] = W2[i];
    }
    if (tid < Hd) { b1s[tid] = b1[tid]; b2s[tid] = b2[tid]; }

    int team = tid >> 8;            // 0/1
    int ttid = tid & 255;
    int ty   = ttid >> 4;           // 0..15 -> 4 rows each
    int tx   = ttid & 15;           // 0..15 -> 8 cols each
    int row0 = ty * 4;
    int col0 = tx * 8;
    int wcol = col0 + 2 * (col0 >> 5);   // padded offset, distinct banks

    float* feat = featb + team * Kn * LDC;
    float* h1s  = h1b   + team * Kn * LDH;
    float* smax = smaxb + team * 16 * Hd;

    for (int base = blockIdx.x * 2; base < Bsz * Mc; base += gridDim.x * 2) {
        int cm = base + team;
        int b  = cm >> 10;
        __syncthreads();  // weights ready (1st iter) / feat,h1,smax reusable

        // gather x features -> feat[k][c]
        const float* xb  = x + (size_t)b * Npt * Cft;
        const int*   nbp = g_nbr + cm * Kn;
#pragma unroll
        for (int j = ttid; j < Kn * 16; j += TEAM_T) {
            int k  = j >> 4;
            int c4 = (j & 15) << 2;
            int nb = __ldg(nbp + k);
            float4 v = *(const float4*)(xb + (size_t)nb * Cft + c4);
            *(float4*)(feat + k * LDC + c4) = v;
        }
        if (ttid < Kn) {
            float cx = g_ctr[cm * 3 + 0], cy = g_ctr[cm * 3 + 1], cz = g_ctr[cm * 3 + 2];
            const float* pb = pos + b * Npt * 3;
            int n3 = __ldg(nbp + ttid) * 3;
            feat[ttid * LDC + 64] = pb[n3 + 0] - cx;
            feat[ttid * LDC + 65] = pb[n3 + 1] - cy;
            feat[ttid * LDC + 66] = pb[n3 + 2] - cz;
        }
        int cnt = __ldg(g_cnt + cm);
        __syncthreads();

        ull acc[4][4];
#pragma unroll
        for (int r = 0; r < 4; r++)
#pragma unroll
            for (int q = 0; q < 4; q++) acc[r][q] = 0ULL;

        // -------- layer 1: feat[64x67] @ W1[67x128] ----------
        {
            const float* a0 = feat + row0 * LDC;
            const float* wp = W1s + wcol;
#pragma unroll 4
            for (int c = 0; c < CIN; c++) {
                ull w0 = *(const ull*)(wp + 0);
                ull w1 = *(const ull*)(wp + 2);
                ull w2 = *(const ull*)(wp + 4);
                ull w3 = *(const ull*)(wp + 6);
                wp += WP;
                ull da0 = dup2(a0[c]);
                ull da1 = dup2(a0[LDC + c]);
                ull da2 = dup2(a0[2 * LDC + c]);
                ull da3 = dup2(a0[3 * LDC + c]);
                acc[0][0] = fma2(da0, w0, acc[0][0]); acc[0][1] = fma2(da0, w1, acc[0][1]);
                acc[0][2] = fma2(da0, w2, acc[0][2]); acc[0][3] = fma2(da0, w3, acc[0][3]);
                acc[1][0] = fma2(da1, w0, acc[1][0]); acc[1][1] = fma2(da1, w1, acc[1][1]);
                acc[1][2] = fma2(da1, w2, acc[1][2]); acc[1][3] = fma2(da1, w3, acc[1][3]);
                acc[2][0] = fma2(da2, w0, acc[2][0]); acc[2][1] = fma2(da2, w1, acc[2][1]);
                acc[2][2] = fma2(da2, w2, acc[2][2]); acc[2][3] = fma2(da2, w3, acc[2][3]);
                acc[3][0] = fma2(da3, w0, acc[3][0]); acc[3][1] = fma2(da3, w1, acc[3][1]);
                acc[3][2] = fma2(da3, w2, acc[3][2]); acc[3][3] = fma2(da3, w3, acc[3][3]);
            }
        }
        // bias + relu + store h1 rows (produced & consumed within this warp)
#pragma unroll
        for (int r = 0; r < 4; r++) {
            float f[8];
#pragma unroll
            for (int q = 0; q < 4; q++) unpk(acc[r][q], f[2 * q], f[2 * q + 1]);
            float* hrow = h1s + (row0 + r) * LDH + col0;
            float4 v0, v1;
            v0.x = fmaxf(f[0] + b1s[col0 + 0], 0.f);
            v0.y = fmaxf(f[1] + b1s[col0 + 1], 0.f);
            v0.z = fmaxf(f[2] + b1s[col0 + 2], 0.f);
            v0.w = fmaxf(f[3] + b1s[col0 + 3], 0.f);
            v1.x = fmaxf(f[4] + b1s[col0 + 4], 0.f);
            v1.y = fmaxf(f[5] + b1s[col0 + 5], 0.f);
            v1.z = fmaxf(f[6] + b1s[col0 + 6], 0.f);
            v1.w = fmaxf(f[7] + b1s[col0 + 7], 0.f);
            *(float4*)(hrow)     = v0;
            *(float4*)(hrow + 4) = v1;
        }
        __syncwarp();

        // -------- layer 2: h1[64x128] @ W2[128x128] ----------
#pragma unroll
        for (int r = 0; r < 4; r++)
#pragma unroll
            for (int q = 0; q < 4; q++) acc[r][q] = 0ULL;
        {
            const float* a0 = h1s + row0 * LDH;
            const float* wp = W2s + wcol;
#pragma unroll 4
            for (int h = 0; h < Hd; h++) {
                ull w0 = *(const ull*)(wp + 0);
                ull w1 = *(const ull*)(wp + 2);
                ull w2 = *(const ull*)(wp + 4);
                ull w3 = *(const ull*)(wp + 6);
                wp += WP;
                ull da0 = dup2(a0[h]);
                ull da1 = dup2(a0[LDH + h]);
                ull da2 = dup2(a0[2 * LDH + h]);
                ull da3 = dup2(a0[3 * LDH + h]);
                acc[0][0] = fma2(da0, w0, acc[0][0]); acc[0][1] = fma2(da0, w1, acc[0][1]);
                acc[0][2] = fma2(da0, w2, acc[0][2]); acc[0][3] = fma2(da0, w3, acc[0][3]);
                acc[1][0] = fma2(da1, w0, acc[1][0]); acc[1][1] = fma2(da1, w1, acc[1][1]);
                acc[1][2] = fma2(da1, w2, acc[1][2]); acc[1][3] = fma2(da1, w3, acc[1][3]);
                acc[2][0] = fma2(da2, w0, acc[2][0]); acc[2][1] = fma2(da2, w1, acc[2][1]);
                acc[2][2] = fma2(da2, w2, acc[2][2]); acc[2][3] = fma2(da2, w3, acc[2][3]);
                acc[3][0] = fma2(da3, w0, acc[3][0]); acc[3][1] = fma2(da3, w1, acc[3][1]);
                acc[3][2] = fma2(da3, w2, acc[3][2]); acc[3][3] = fma2(da3, w3, acc[3][3]);
            }
        }

        // -------- bias + relu + masked max (mask only here) --------------
        float cmax[8];
#pragma unroll
        for (int q = 0; q < 8; q++) cmax[q] = -1e30f;
        int rmax = cnt - row0;
        if (rmax > 4) rmax = 4;
        for (int r = 0; r < rmax; r++) {
            float f[8];
#pragma unroll
            for (int q = 0; q < 4; q++) unpk(acc[r][q], f[2 * q], f[2 * q + 1]);
#pragma unroll
            for (int q = 0; q < 8; q++) {
                float hv = fmaxf(f[q] + b2s[col0 + q], 0.f);
                cmax[q]  = fmaxf(cmax[q], hv);
            }
        }
        {
            float4 v0, v1;
            v0.x = cmax[0]; v0.y = cmax[1]; v0.z = cmax[2]; v0.w = cmax[3];
            v1.x = cmax[4]; v1.y = cmax[5]; v1.z = cmax[6]; v1.w = cmax[7];
            *(float4*)(smax + ty * Hd + col0)     = v0;
            *(float4*)(smax + ty * Hd + col0 + 4) = v1;
        }
        __syncthreads();
        if (ttid < Hd) {
            float mv = -1e30f;
#pragma unroll
            for (int yy = 0; yy < 16; yy++) mv = fmaxf(mv, smax[yy * Hd + ttid]);
            out[(size_t)cm * Hd + ttid] = (cnt > 0) ? mv : 0.0f;
        }
    }
}

// ============================ launch ======================================
extern "C" void kernel_launch(void* const* d_in, const int* in_sizes, int n_in,
                              void* d_out, int out_size) {
    const float* x   = (const float*)d_in[0];
    const float* pos = (const float*)d_in[1];
    const float* W1  = (const float*)d_in[2];
    const float* b1  = (const float*)d_in[3];
    const float* W2  = (const float*)d_in[4];
    const float* b2  = (const float*)d_in[5];
    float* out = (float*)d_out;

    float* poss;
    if (out_size >= Bsz * Mc * (Hd + 3)) {
        poss = out + (size_t)Bsz * Mc * Hd;
    } else {
        void* tmp = nullptr;
        cudaGetSymbolAddress(&tmp, g_poss_dump);
        poss = (float*)tmp;
    }

    cudaFuncSetAttribute(mlp_kernel, cudaFuncAttributeMaxDynamicSharedMemorySize,
                         SMEM_BYTES);
    cudaFuncSetAttribute(fps_kernel, cudaFuncAttributeMaxDynamicSharedMemorySize,
                         3 * Npt * 4);

    fps_kernel<<<Bsz, FPS_T, 3 * Npt * 4>>>(pos);
    query_kernel<<<(Bsz * Mc) / QWARPS, QWARPS * 32>>>(pos, poss);
    mlp_kernel<<<152, MLP_T, SMEM_BYTES>>>(x, pos, W1, b1, W2, b2, out);
}

// round 8
// speedup vs baseline: 3.3300x; 1.4044x over previous
#include <cuda_runtime.h>
#include <cuda_bf16.h>
#include <float.h>
#include <stdint.h>

#define Bsz 16
#define Npt 4096
#define Cft 64
#define Mc  1024
#define Kn  64
#define Hd  128
#define CIN 67

__device__ int   g_idx[Bsz*Mc];
__device__ int   g_nbr[Bsz*Mc*Kn];
__device__ int   g_cnt[Bsz*Mc];
__device__ float g_ctr[Bsz*Mc*3];
__device__ float g_poss_dump[Bsz*Mc*3];

// ============================ 1) FPS (512 thr x 8 pts) ====================
#define FPS_T 512
#define FPPT 8
extern __shared__ float fps_sm[];

__global__ __launch_bounds__(FPS_T) void fps_kernel(const float* __restrict__ pos) {
    float* spx = fps_sm;
    float* spy = spx + Npt;
    float* spz = spy + Npt;
    __shared__ unsigned swv[2][16];
    __shared__ unsigned swc[2][16];

    int b = blockIdx.x;
    const float* p = pos + b * Npt * 3;
    int t = threadIdx.x, lane = t & 31, w = t >> 5;

    float px[FPPT], py[FPPT], pz[FPPT], dd[FPPT];
#pragma unroll
    for (int j = 0; j < FPPT; j++) {
        int i = t + j * FPS_T;
        float xx = p[i*3+0], yy = p[i*3+1], zz = p[i*3+2];
        px[j] = xx; py[j] = yy; pz[j] = zz;
        spx[i] = xx; spy[i] = yy; spz[i] = zz;
        dd[j] = FLT_MAX;
    }
    if (t == 0) g_idx[b * Mc] = 0;
    __syncthreads();

    int last = 0, par = 0;
    for (int s = 1; s < Mc; s++) {
        float lx = spx[last], ly = spy[last], lz = spz[last];
        unsigned vmx = 0u;
#pragma unroll
        for (int j = 0; j < FPPT; j++) {
            float dx = __fsub_rn(px[j], lx);
            float dy = __fsub_rn(py[j], ly);
            float dz = __fsub_rn(pz[j], lz);
            float d  = __fadd_rn(__fadd_rn(__fmul_rn(dx,dx), __fmul_rn(dy,dy)),
                                 __fmul_rn(dz,dz));
            float v = fminf(dd[j], d);
            dd[j] = v;
            unsigned vu = __float_as_uint(v);
            vmx = vmx > vu ? vmx : vu;
        }
        unsigned cand = 0x7fffffffu;
#pragma unroll
        for (int j = FPPT - 1; j >= 0; j--)
            if (__float_as_uint(dd[j]) == vmx) cand = (unsigned)(t + j * FPS_T);
        unsigned wmax = __reduce_max_sync(0xffffffffu, vmx);
        unsigned csel = (vmx == wmax) ? cand : 0x7fffffffu;
        unsigned wcnd = __reduce_min_sync(0xffffffffu, csel);
        if (lane == 0) { swv[par][w] = wmax; swc[par][w] = wcnd; }
        __syncthreads();
        unsigned vv = (lane < 16) ? swv[par][lane] : 0u;
        unsigned cc = (lane < 16) ? swc[par][lane] : 0x7fffffffu;
        unsigned vm = __reduce_max_sync(0xffffffffu, vv);
        unsigned cm = __reduce_min_sync(0xffffffffu, (vv == vm) ? cc : 0x7fffffffu);
        last = (int)cm;
        par ^= 1;
        if (t == 0) g_idx[b * Mc + s] = last;
    }
}

// ============================ 2) radius query (unchanged) =================
#define QWARPS 8
__global__ __launch_bounds__(QWARPS * 32) void query_kernel(
    const float* __restrict__ pos, float* __restrict__ poss_out) {
    int cm   = blockIdx.x * QWARPS + (threadIdx.x >> 5);
    int lane = threadIdx.x & 31;
    int b    = cm >> 10;
    const float* p = pos + b * Npt * 3;

    int   ci = g_idx[cm];
    float sx = p[ci*3+0], sy = p[ci*3+1], sz = p[ci*3+2];
    if (lane == 0) {
        poss_out[cm*3+0] = sx; poss_out[cm*3+1] = sy; poss_out[cm*3+2] = sz;
        g_ctr[cm*3+0] = sx; g_ctr[cm*3+1] = sy; g_ctr[cm*3+2] = sz;
    }
    float sn = __fadd_rn(__fadd_rn(__fmul_rn(sx,sx), __fmul_rn(sy,sy)),
                         __fmul_rn(sz,sz));
    const float R2 = 0.2f * 0.2f;

    int cnt = 0;
    for (int base = 0; base < Npt; base += 32) {
        int   i = base + lane;
        float xx = p[i*3+0], yy = p[i*3+1], zz = p[i*3+2];
        float pn = __fadd_rn(__fadd_rn(__fmul_rn(xx,xx), __fmul_rn(yy,yy)),
                             __fmul_rn(zz,zz));
        float dot = __fadd_rn(__fadd_rn(__fmul_rn(sx,xx), __fmul_rn(sy,yy)),
                              __fmul_rn(sz,zz));
        float d2 = __fsub_rn(__fadd_rn(sn, pn), __fmul_rn(2.0f, dot));
        bool  in = (d2 <= R2);
        unsigned ball = __ballot_sync(0xffffffffu, in);
        if (in) {
            int ppos = cnt + __popc(ball & ((1u << lane) - 1u));
            if (ppos < Kn) g_nbr[cm * Kn + ppos] = i;
        }
        cnt += __popc(ball);
        if (cnt >= Kn) break;
    }
    if (cnt > Kn) cnt = Kn;
    for (int k = cnt + lane; k < Kn; k += 32) g_nbr[cm * Kn + k] = 0;
    if (lane == 0) g_cnt[cm] = cnt;
}

// ============================ 3) MLP via mma.sync bf16x3 ==================
// 1 block/SM, 256 thr (8 warps). Per iter: 2 centers (M=128 rows).
// Warp w owns rows 16w..16w+15 (all feat/h1 smem traffic warp-local).
// Layers: D = Ah*Bh + Ah*Bl + Al*Bh  (bf16 split, fp32 accum).
// W stored [k][n] bf16, pitch 136 halves (272B) -> conflict-free ldmatrix.

#define PITCH 272          // bytes per row (136 halves)
#define OFF_W1H 0
#define OFF_W1L 21760
#define OFF_W2H 43520
#define OFF_W2L 78336
#define OFF_FH  113152
#define OFF_FL  147968
#define OFF_B1  182784
#define OFF_B2  183296
#define OFF_WMX 183808
#define MLP_SMEM 187904

__device__ __forceinline__ uint32_t smem_u32(const void* p) {
    uint32_t a;
    asm("{ .reg .u64 t; cvta.to.shared.u64 t, %1; cvt.u32.u64 %0, t; }"
        : "=r"(a) : "l"(p));
    return a;
}
__device__ __forceinline__ void ldsm_x4(uint32_t addr, uint32_t* r) {
    asm volatile("ldmatrix.sync.aligned.m8n8.x4.shared.b16 {%0,%1,%2,%3}, [%4];"
        : "=r"(r[0]), "=r"(r[1]), "=r"(r[2]), "=r"(r[3]) : "r"(addr));
}
__device__ __forceinline__ void ldsm_x2t(uint32_t addr, uint32_t* r) {
    asm volatile("ldmatrix.sync.aligned.m8n8.x2.trans.shared.b16 {%0,%1}, [%2];"
        : "=r"(r[0]), "=r"(r[1]) : "r"(addr));
}
__device__ __forceinline__ void mma16816(float* d, const uint32_t* a, const uint32_t* b) {
    asm volatile("mma.sync.aligned.m16n8k16.row.col.f32.bf16.bf16.f32 "
        "{%0,%1,%2,%3}, {%4,%5,%6,%7}, {%8,%9}, {%0,%1,%2,%3};"
        : "+f"(d[0]), "+f"(d[1]), "+f"(d[2]), "+f"(d[3])
        : "r"(a[0]), "r"(a[1]), "r"(a[2]), "r"(a[3]), "r"(b[0]), "r"(b[1]));
}
__device__ __forceinline__ void pack_hilo(float v0, float v1, uint32_t& hi, uint32_t& lo) {
    __nv_bfloat16 h0 = __float2bfloat16(v0), h1 = __float2bfloat16(v1);
    __nv_bfloat162 hh; hh.x = h0; hh.y = h1;
    hi = *(uint32_t*)&hh;
    __nv_bfloat162 gg;
    gg.x = __float2bfloat16(v0 - __bfloat162float(h0));
    gg.y = __float2bfloat16(v1 - __bfloat162float(h1));
    lo = *(uint32_t*)&gg;
}

template <int KSTEPS>
__device__ __forceinline__ void do_layer(char* sm, int offAh, int offAl,
                                         int offBh, int offBl,
                                         int wrow0, int lane, float d[16][4]) {
    uint32_t aHi = smem_u32(sm + offAh) + (uint32_t)(wrow0 + (lane & 15)) * PITCH
                   + ((lane >> 4) << 4);
    uint32_t aLo = smem_u32(sm + offAl) + (uint32_t)(wrow0 + (lane & 15)) * PITCH
                   + ((lane >> 4) << 4);
    uint32_t bHi0 = smem_u32(sm + offBh) + (uint32_t)(lane & 15) * PITCH;
    uint32_t bLo0 = smem_u32(sm + offBl) + (uint32_t)(lane & 15) * PITCH;
#pragma unroll
    for (int ks = 0; ks < KSTEPS; ks++) {
        uint32_t ah[4], al[4];
        ldsm_x4(aHi + ks * 32, ah);
        ldsm_x4(aLo + ks * 32, al);
        uint32_t bh_b = bHi0 + (uint32_t)ks * 16 * PITCH;
        uint32_t bl_b = bLo0 + (uint32_t)ks * 16 * PITCH;
#pragma unroll
        for (int nt = 0; nt < 16; nt++) {
            uint32_t bh[2], bl[2];
            ldsm_x2t(bh_b + nt * 16, bh);
            ldsm_x2t(bl_b + nt * 16, bl);
            mma16816(d[nt], ah, bh);
            mma16816(d[nt], ah, bl);
            mma16816(d[nt], al, bh);
        }
    }
}

extern __shared__ __align__(128) char mlps[];

__global__ __launch_bounds__(256, 1) void mlp_kernel(
    const float* __restrict__ x, const float* __restrict__ pos,
    const float* __restrict__ W1, const float* __restrict__ b1,
    const float* __restrict__ W2, const float* __restrict__ b2,
    float* __restrict__ out) {
    char* sm = mlps;
    float* b1s = (float*)(sm + OFF_B1);
    float* b2s = (float*)(sm + OFF_B2);
    float* wmx = (float*)(sm + OFF_WMX);

    int tid = threadIdx.x, lane = tid & 31, warp = tid >> 5;
    int wrow0 = warp * 16;

    // ---- stage weights hi/lo into [k][n] pitch-136 layout (once) --------
    for (int i = tid; i < 80 * 128; i += 256) {
        int kk = i >> 7, n = i & 127;
        float v = (kk < CIN) ? W1[kk * Hd + n] : 0.f;
        __nv_bfloat16 hv = __float2bfloat16(v);
        *(__nv_bfloat16*)(sm + OFF_W1H + kk * PITCH + n * 2) = hv;
        *(__nv_bfloat16*)(sm + OFF_W1L + kk * PITCH + n * 2) =
            __float2bfloat16(v - __bfloat162float(hv));
    }
    for (int i = tid; i < 128 * 128; i += 256) {
        int kk = i >> 7, n = i & 127;
        float v = W2[kk * Hd + n];
        __nv_bfloat16 hv = __float2bfloat16(v);
        *(__nv_bfloat16*)(sm + OFF_W2H + kk * PITCH + n * 2) = hv;
        *(__nv_bfloat16*)(sm + OFF_W2L + kk * PITCH + n * 2) =
            __float2bfloat16(v - __bfloat162float(hv));
    }
    if (tid < Hd) { b1s[tid] = b1[tid]; b2s[tid] = b2[tid]; }
    __syncthreads();

    for (int bc = blockIdx.x * 2; bc < Bsz * Mc; bc += gridDim.x * 2) {
        // ---- gather: rows are warp-local (warp w <-> rows 16w..16w+15) --
        {
            int r = tid >> 1, h = tid & 1;
            int cm = bc + (r >> 6);
            int bb = cm >> 10;
            int k  = r & 63;
            int nb = __ldg(g_nbr + cm * Kn + k);
            const float* xr = x + ((size_t)bb * Npt + nb) * Cft + h * 32;
            char* fh = sm + OFF_FH + r * PITCH + h * 64;
            char* fl = sm + OFF_FL + r * PITCH + h * 64;
#pragma unroll
            for (int j = 0; j < 8; j++) {
                float4 v = *(const float4*)(xr + j * 4);
                uint32_t h0, l0, h1v, l1v;
                pack_hilo(v.x, v.y, h0, l0);
                pack_hilo(v.z, v.w, h1v, l1v);
                *(uint32_t*)(fh + j * 8)     = h0;
                *(uint32_t*)(fh + j * 8 + 4) = h1v;
                *(uint32_t*)(fl + j * 8)     = l0;
                *(uint32_t*)(fl + j * 8 + 4) = l1v;
            }
            if (h == 0) {  // cols 64..79: pos diffs + zero pad
                const float* pb = pos + bb * Npt * 3;
                float pd0 = pb[nb*3+0] - g_ctr[cm*3+0];
                float pd1 = pb[nb*3+1] - g_ctr[cm*3+1];
                float pd2 = pb[nb*3+2] - g_ctr[cm*3+2];
                char* fh2 = sm + OFF_FH + r * PITCH + 128;
                char* fl2 = sm + OFF_FL + r * PITCH + 128;
                uint32_t h0, l0, h1v, l1v;
                pack_hilo(pd0, pd1, h0, l0);
                pack_hilo(pd2, 0.f, h1v, l1v);
                *(uint32_t*)(fh2)     = h0;  *(uint32_t*)(fh2 + 4) = h1v;
                *(uint32_t*)(fl2)     = l0;  *(uint32_t*)(fl2 + 4) = l1v;
#pragma unroll
                for (int j = 2; j < 8; j++) {
                    *(uint32_t*)(fh2 + j * 4) = 0u;
                    *(uint32_t*)(fl2 + j * 4) = 0u;
                }
            }
        }
        __syncwarp();

        // ---- layer 1: K=80 (5 ksteps) -----------------------------------
        float d[16][4];
#pragma unroll
        for (int nt = 0; nt < 16; nt++)
#pragma unroll
            for (int q = 0; q < 4; q++) d[nt][q] = 0.f;
        do_layer<5>(sm, OFF_FH, OFF_FL, OFF_W1H, OFF_W1L, wrow0, lane, d);

        // ---- epilogue 1: h1 = relu(D+b1) -> overwrite feat buffers ------
        {
            int r0 = wrow0 + (lane >> 2);
#pragma unroll
            for (int nt = 0; nt < 16; nt++) {
                int c0 = nt * 8 + (lane & 3) * 2;
                float v00 = fmaxf(d[nt][0] + b1s[c0],     0.f);
                float v01 = fmaxf(d[nt][1] + b1s[c0 + 1], 0.f);
                float v10 = fmaxf(d[nt][2] + b1s[c0],     0.f);
                float v11 = fmaxf(d[nt][3] + b1s[c0 + 1], 0.f);
                uint32_t h0, l0, h1v, l1v;
                pack_hilo(v00, v01, h0, l0);
                pack_hilo(v10, v11, h1v, l1v);
                *(uint32_t*)(sm + OFF_FH + r0 * PITCH + c0 * 2)       = h0;
                *(uint32_t*)(sm + OFF_FL + r0 * PITCH + c0 * 2)       = l0;
                *(uint32_t*)(sm + OFF_FH + (r0 + 8) * PITCH + c0 * 2) = h1v;
                *(uint32_t*)(sm + OFF_FL + (r0 + 8) * PITCH + c0 * 2) = l1v;
            }
        }
        __syncwarp();

        // ---- layer 2: K=128 (8 ksteps) ----------------------------------
#pragma unroll
        for (int nt = 0; nt < 16; nt++)
#pragma unroll
            for (int q = 0; q < 4; q++) d[nt][q] = 0.f;
        do_layer<8>(sm, OFF_FH, OFF_FL, OFF_W2H, OFF_W2L, wrow0, lane, d);

        // ---- epilogue 2: bias+relu, mask, column max --------------------
        {
            int cnt_w = __ldg(g_cnt + bc + (warp >> 2));
            int k0 = (wrow0 & 63) + (lane >> 2);
            bool va = k0 < cnt_w, vb = (k0 + 8) < cnt_w;
#pragma unroll
            for (int nt = 0; nt < 16; nt++) {
                int c0 = nt * 8 + (lane & 3) * 2;
                float m0 = fmaxf(va ? fmaxf(d[nt][0] + b2s[c0], 0.f) : 0.f,
                                 vb ? fmaxf(d[nt][2] + b2s[c0], 0.f) : 0.f);
                float m1 = fmaxf(va ? fmaxf(d[nt][1] + b2s[c0 + 1], 0.f) : 0.f,
                                 vb ? fmaxf(d[nt][3] + b2s[c0 + 1], 0.f) : 0.f);
#pragma unroll
                for (int o = 4; o <= 16; o <<= 1) {
                    m0 = fmaxf(m0, __shfl_xor_sync(0xffffffffu, m0, o));
                    m1 = fmaxf(m1, __shfl_xor_sync(0xffffffffu, m1, o));
                }
                if (lane < 4) {
                    wmx[warp * 128 + c0]     = m0;
                    wmx[warp * 128 + c0 + 1] = m1;
                }
            }
        }
        __syncthreads();
        {
            int col = tid & 127, ctr = tid >> 7;
            float mv = fmaxf(
                fmaxf(wmx[(ctr * 4 + 0) * 128 + col], wmx[(ctr * 4 + 1) * 128 + col]),
                fmaxf(wmx[(ctr * 4 + 2) * 128 + col], wmx[(ctr * 4 + 3) * 128 + col]));
            int cmo = bc + ctr;
            out[(size_t)cmo * Hd + col] = (__ldg(g_cnt + cmo) > 0) ? mv : 0.f;
        }
        __syncthreads();
    }
}

// ============================ launch ======================================
extern "C" void kernel_launch(void* const* d_in, const int* in_sizes, int n_in,
                              void* d_out, int out_size) {
    const float* x   = (const float*)d_in[0];
    const float* pos = (const float*)d_in[1];
    const float* W1  = (const float*)d_in[2];
    const float* b1  = (const float*)d_in[3];
    const float* W2  = (const float*)d_in[4];
    const float* b2  = (const float*)d_in[5];
    float* out = (float*)d_out;

    float* poss;
    if (out_size >= Bsz * Mc * (Hd + 3)) {
        poss = out + (size_t)Bsz * Mc * Hd;
    } else {
        void* tmp = nullptr;
        cudaGetSymbolAddress(&tmp, g_poss_dump);
        poss = (float*)tmp;
    }

    cudaFuncSetAttribute(mlp_kernel, cudaFuncAttributeMaxDynamicSharedMemorySize, MLP_SMEM);
    cudaFuncSetAttribute(fps_kernel, cudaFuncAttributeMaxDynamicSharedMemorySize, 3 * Npt * 4);

    fps_kernel<<<Bsz, FPS_T, 3 * Npt * 4>>>(pos);
    query_kernel<<<(Bsz * Mc) / QWARPS, QWARPS * 32>>>(pos, poss);
    mlp_kernel<<<152, 256, MLP_SMEM>>>(x, pos, W1, b1, W2, b2, out);
}

// round 9
// speedup vs baseline: 3.5042x; 1.0523x over previous
#include <cuda_runtime.h>
#include <cuda_bf16.h>
#include <float.h>
#include <stdint.h>

#define Bsz 16
#define Npt 4096
#define Cft 64
#define Mc  1024
#define Kn  64
#define Hd  128
#define CIN 67

__device__ int   g_idx[Bsz*Mc];
__device__ int   g_nbr[Bsz*Mc*Kn];
__device__ int   g_cnt[Bsz*Mc];
__device__ float g_ctr[Bsz*Mc*3];
__device__ float g_poss_dump[Bsz*Mc*3];

// ============================ 1) FPS (R5 version, 403us) ==================
#define FPS_T 1024
#define FPPT 4
extern __shared__ float fps_sm[];

__global__ __launch_bounds__(FPS_T) void fps_kernel(const float* __restrict__ pos) {
    float* spx = fps_sm;
    float* spy = spx + Npt;
    float* spz = spy + Npt;
    __shared__ unsigned swv[2][32];
    __shared__ unsigned swc[2][32];

    int b = blockIdx.x;
    const float* p = pos + b * Npt * 3;
    int t = threadIdx.x, lane = t & 31, w = t >> 5;

    float px[FPPT], py[FPPT], pz[FPPT], dd[FPPT];
#pragma unroll
    for (int j = 0; j < FPPT; j++) {
        int i = t + j * FPS_T;
        float xx = p[i*3+0], yy = p[i*3+1], zz = p[i*3+2];
        px[j] = xx; py[j] = yy; pz[j] = zz;
        spx[i] = xx; spy[i] = yy; spz[i] = zz;
        dd[j] = FLT_MAX;
    }
    if (t == 0) g_idx[b * Mc] = 0;
    __syncthreads();

    int last = 0, par = 0;
    for (int s = 1; s < Mc; s++) {
        float lx = spx[last], ly = spy[last], lz = spz[last];
        unsigned vmx = 0u;
#pragma unroll
        for (int j = 0; j < FPPT; j++) {
            float dx = __fsub_rn(px[j], lx);
            float dy = __fsub_rn(py[j], ly);
            float dz = __fsub_rn(pz[j], lz);
            float d  = __fadd_rn(__fadd_rn(__fmul_rn(dx,dx), __fmul_rn(dy,dy)),
                                 __fmul_rn(dz,dz));
            float v = fminf(dd[j], d);
            dd[j] = v;
            unsigned vu = __float_as_uint(v);
            vmx = vmx > vu ? vmx : vu;
        }
        unsigned cand = 0x7fffffffu;
#pragma unroll
        for (int j = FPPT - 1; j >= 0; j--)
            if (__float_as_uint(dd[j]) == vmx) cand = (unsigned)(t + j * FPS_T);
        unsigned wmax = __reduce_max_sync(0xffffffffu, vmx);
        unsigned csel = (vmx == wmax) ? cand : 0x7fffffffu;
        unsigned wcnd = __reduce_min_sync(0xffffffffu, csel);
        if (lane == 0) { swv[par][w] = wmax; swc[par][w] = wcnd; }
        __syncthreads();
        unsigned vv = swv[par][lane], cc = swc[par][lane];
        unsigned vm = __reduce_max_sync(0xffffffffu, vv);
        unsigned cm = __reduce_min_sync(0xffffffffu, (vv == vm) ? cc : 0x7fffffffu);
        last = (int)cm;
        par ^= 1;
        if (t == 0) g_idx[b * Mc + s] = last;
    }
}

// ============================ 2) radius query (unchanged) =================
#define QWARPS 8
__global__ __launch_bounds__(QWARPS * 32) void query_kernel(
    const float* __restrict__ pos, float* __restrict__ poss_out) {
    int cm   = blockIdx.x * QWARPS + (threadIdx.x >> 5);
    int lane = threadIdx.x & 31;
    int b    = cm >> 10;
    const float* p = pos + b * Npt * 3;

    int   ci = g_idx[cm];
    float sx = p[ci*3+0], sy = p[ci*3+1], sz = p[ci*3+2];
    if (lane == 0) {
        poss_out[cm*3+0] = sx; poss_out[cm*3+1] = sy; poss_out[cm*3+2] = sz;
        g_ctr[cm*3+0] = sx; g_ctr[cm*3+1] = sy; g_ctr[cm*3+2] = sz;
    }
    float sn = __fadd_rn(__fadd_rn(__fmul_rn(sx,sx), __fmul_rn(sy,sy)),
                         __fmul_rn(sz,sz));
    const float R2 = 0.2f * 0.2f;

    int cnt = 0;
    for (int base = 0; base < Npt; base += 32) {
        int   i = base + lane;
        float xx = p[i*3+0], yy = p[i*3+1], zz = p[i*3+2];
        float pn = __fadd_rn(__fadd_rn(__fmul_rn(xx,xx), __fmul_rn(yy,yy)),
                             __fmul_rn(zz,zz));
        float dot = __fadd_rn(__fadd_rn(__fmul_rn(sx,xx), __fmul_rn(sy,yy)),
                              __fmul_rn(sz,zz));
        float d2 = __fsub_rn(__fadd_rn(sn, pn), __fmul_rn(2.0f, dot));
        bool  in = (d2 <= R2);
        unsigned ball = __ballot_sync(0xffffffffu, in);
        if (in) {
            int ppos = cnt + __popc(ball & ((1u << lane) - 1u));
            if (ppos < Kn) g_nbr[cm * Kn + ppos] = i;
        }
        cnt += __popc(ball);
        if (cnt >= Kn) break;
    }
    if (cnt > Kn) cnt = Kn;
    for (int k = cnt + lane; k < Kn; k += 32) g_nbr[cm * Kn + k] = 0;
    if (lane == 0) g_cnt[cm] = cnt;
}

// ============================ 3) MLP via mma.sync bf16x3 ==================
// Same structure as R8 (passing), except B fragments are loaded with
// ldmatrix.x4.trans (one instr covers 2 n-tiles x full k16) -> B LDSM
// count halves. mma order/operands identical -> bit-identical results.

#define PITCH 272          // bytes per row (136 halves)
#define OFF_W1H 0
#define OFF_W1L 21760
#define OFF_W2H 43520
#define OFF_W2L 78336
#define OFF_FH  113152
#define OFF_FL  147968
#define OFF_B1  182784
#define OFF_B2  183296
#define OFF_WMX 183808
#define MLP_SMEM 187904

__device__ __forceinline__ uint32_t smem_u32(const void* p) {
    uint32_t a;
    asm("{ .reg .u64 t; cvta.to.shared.u64 t, %1; cvt.u32.u64 %0, t; }"
        : "=r"(a) : "l"(p));
    return a;
}
__device__ __forceinline__ void ldsm_x4(uint32_t addr, uint32_t* r) {
    asm volatile("ldmatrix.sync.aligned.m8n8.x4.shared.b16 {%0,%1,%2,%3}, [%4];"
        : "=r"(r[0]), "=r"(r[1]), "=r"(r[2]), "=r"(r[3]) : "r"(addr));
}
__device__ __forceinline__ void ldsm_x4t(uint32_t addr, uint32_t* r) {
    asm volatile("ldmatrix.sync.aligned.m8n8.x4.trans.shared.b16 {%0,%1,%2,%3}, [%4];"
        : "=r"(r[0]), "=r"(r[1]), "=r"(r[2]), "=r"(r[3]) : "r"(addr));
}
__device__ __forceinline__ void mma16816(float* d, const uint32_t* a, const uint32_t* b) {
    asm volatile("mma.sync.aligned.m16n8k16.row.col.f32.bf16.bf16.f32 "
        "{%0,%1,%2,%3}, {%4,%5,%6,%7}, {%8,%9}, {%0,%1,%2,%3};"
        : "+f"(d[0]), "+f"(d[1]), "+f"(d[2]), "+f"(d[3])
        : "r"(a[0]), "r"(a[1]), "r"(a[2]), "r"(a[3]), "r"(b[0]), "r"(b[1]));
}
__device__ __forceinline__ void pack_hilo(float v0, float v1, uint32_t& hi, uint32_t& lo) {
    __nv_bfloat16 h0 = __float2bfloat16(v0), h1 = __float2bfloat16(v1);
    __nv_bfloat162 hh; hh.x = h0; hh.y = h1;
    hi = *(uint32_t*)&hh;
    __nv_bfloat162 gg;
    gg.x = __float2bfloat16(v0 - __bfloat162float(h0));
    gg.y = __float2bfloat16(v1 - __bfloat162float(h1));
    lo = *(uint32_t*)&gg;
}

template <int KSTEPS>
__device__ __forceinline__ void do_layer(char* sm, int offAh, int offAl,
                                         int offBh, int offBl,
                                         int wrow0, int lane, float d[16][4]) {
    uint32_t aHi = smem_u32(sm + offAh) + (uint32_t)(wrow0 + (lane & 15)) * PITCH
                   + ((lane >> 4) << 4);
    uint32_t aLo = smem_u32(sm + offAl) + (uint32_t)(wrow0 + (lane & 15)) * PITCH
                   + ((lane >> 4) << 4);
    // x4.trans lane map: matrix mi = lane>>3; k-row = (mi&1)*8 + (lane&7);
    // n-col byte = (mi>>1)*8*2. Covers n-tiles {ntp*2, ntp*2+1} x k16.
    uint32_t bprow = (uint32_t)((lane & 7) + ((lane >> 3) & 1) * 8) * PITCH
                     + (uint32_t)((lane >> 4) << 4);
    uint32_t bHi0 = smem_u32(sm + offBh) + bprow;
    uint32_t bLo0 = smem_u32(sm + offBl) + bprow;
#pragma unroll
    for (int ks = 0; ks < KSTEPS; ks++) {
        uint32_t ah[4], al[4];
        ldsm_x4(aHi + ks * 32, ah);
        ldsm_x4(aLo + ks * 32, al);
        uint32_t bh_b = bHi0 + (uint32_t)ks * 16 * PITCH;
        uint32_t bl_b = bLo0 + (uint32_t)ks * 16 * PITCH;
#pragma unroll
        for (int ntp = 0; ntp < 8; ntp++) {
            uint32_t bh[4], bl[4];
            ldsm_x4t(bh_b + ntp * 32, bh);
            ldsm_x4t(bl_b + ntp * 32, bl);
            mma16816(d[2*ntp],     ah, bh);
            mma16816(d[2*ntp],     ah, bl);
            mma16816(d[2*ntp],     al, bh);
            mma16816(d[2*ntp + 1], ah, bh + 2);
            mma16816(d[2*ntp + 1], ah, bl + 2);
            mma16816(d[2*ntp + 1], al, bh + 2);
        }
    }
}

extern __shared__ __align__(128) char mlps[];

__global__ __launch_bounds__(256, 1) void mlp_kernel(
    const float* __restrict__ x, const float* __restrict__ pos,
    const float* __restrict__ W1, const float* __restrict__ b1,
    const float* __restrict__ W2, const float* __restrict__ b2,
    float* __restrict__ out) {
    char* sm = mlps;
    float* b1s = (float*)(sm + OFF_B1);
    float* b2s = (float*)(sm + OFF_B2);
    float* wmx = (float*)(sm + OFF_WMX);

    int tid = threadIdx.x, lane = tid & 31, warp = tid >> 5;
    int wrow0 = warp * 16;

    // ---- stage weights hi/lo into [k][n] pitch-136 layout (once) --------
    for (int i = tid; i < 80 * 128; i += 256) {
        int kk = i >> 7, n = i & 127;
        float v = (kk < CIN) ? W1[kk * Hd + n] : 0.f;
        __nv_bfloat16 hv = __float2bfloat16(v);
        *(__nv_bfloat16*)(sm + OFF_W1H + kk * PITCH + n * 2) = hv;
        *(__nv_bfloat16*)(sm + OFF_W1L + kk * PITCH + n * 2) =
            __float2bfloat16(v - __bfloat162float(hv));
    }
    for (int i = tid; i < 128 * 128; i += 256) {
        int kk = i >> 7, n = i & 127;
        float v = W2[kk * Hd + n];
        __nv_bfloat16 hv = __float2bfloat16(v);
        *(__nv_bfloat16*)(sm + OFF_W2H + kk * PITCH + n * 2) = hv;
        *(__nv_bfloat16*)(sm + OFF_W2L + kk * PITCH + n * 2) =
            __float2bfloat16(v - __bfloat162float(hv));
    }
    if (tid < Hd) { b1s[tid] = b1[tid]; b2s[tid] = b2[tid]; }
    __syncthreads();

    for (int bc = blockIdx.x * 2; bc < Bsz * Mc; bc += gridDim.x * 2) {
        // ---- gather: rows are warp-local (warp w <-> rows 16w..16w+15) --
        {
            int r = tid >> 1, h = tid & 1;
            int cm = bc + (r >> 6);
            int bb = cm >> 10;
            int k  = r & 63;
            int nb = __ldg(g_nbr + cm * Kn + k);
            const float* xr = x + ((size_t)bb * Npt + nb) * Cft + h * 32;
            char* fh = sm + OFF_FH + r * PITCH + h * 64;
            char* fl = sm + OFF_FL + r * PITCH + h * 64;
#pragma unroll
            for (int j = 0; j < 8; j++) {
                float4 v = *(const float4*)(xr + j * 4);
                uint32_t h0, l0, h1v, l1v;
                pack_hilo(v.x, v.y, h0, l0);
                pack_hilo(v.z, v.w, h1v, l1v);
                *(uint32_t*)(fh + j * 8)     = h0;
                *(uint32_t*)(fh + j * 8 + 4) = h1v;
                *(uint32_t*)(fl + j * 8)     = l0;
                *(uint32_t*)(fl + j * 8 + 4) = l1v;
            }
            if (h == 0) {  // cols 64..79: pos diffs + zero pad
                const float* pb = pos + bb * Npt * 3;
                float pd0 = pb[nb*3+0] - g_ctr[cm*3+0];
                float pd1 = pb[nb*3+1] - g_ctr[cm*3+1];
                float pd2 = pb[nb*3+2] - g_ctr[cm*3+2];
                char* fh2 = sm + OFF_FH + r * PITCH + 128;
                char* fl2 = sm + OFF_FL + r * PITCH + 128;
                uint32_t h0, l0, h1v, l1v;
                pack_hilo(pd0, pd1, h0, l0);
                pack_hilo(pd2, 0.f, h1v, l1v);
                *(uint32_t*)(fh2)     = h0;  *(uint32_t*)(fh2 + 4) = h1v;
                *(uint32_t*)(fl2)     = l0;  *(uint32_t*)(fl2 + 4) = l1v;
#pragma unroll
                for (int j = 2; j < 8; j++) {
                    *(uint32_t*)(fh2 + j * 4) = 0u;
                    *(uint32_t*)(fl2 + j * 4) = 0u;
                }
            }
        }
        __syncwarp();

        // ---- layer 1: K=80 (5 ksteps) -----------------------------------
        float d[16][4];
#pragma unroll
        for (int nt = 0; nt < 16; nt++)
#pragma unroll
            for (int q = 0; q < 4; q++) d[nt][q] = 0.f;
        do_layer<5>(sm, OFF_FH, OFF_FL, OFF_W1H, OFF_W1L, wrow0, lane, d);

        // ---- epilogue 1: h1 = relu(D+b1) -> overwrite feat buffers ------
        {
            int r0 = wrow0 + (lane >> 2);
#pragma unroll
            for (int nt = 0; nt < 16; nt++) {
                int c0 = nt * 8 + (lane & 3) * 2;
                float v00 = fmaxf(d[nt][0] + b1s[c0],     0.f);
                float v01 = fmaxf(d[nt][1] + b1s[c0 + 1], 0.f);
                float v10 = fmaxf(d[nt][2] + b1s[c0],     0.f);
                float v11 = fmaxf(d[nt][3] + b1s[c0 + 1], 0.f);
                uint32_t h0, l0, h1v, l1v;
                pack_hilo(v00, v01, h0, l0);
                pack_hilo(v10, v11, h1v, l1v);
                *(uint32_t*)(sm + OFF_FH + r0 * PITCH + c0 * 2)       = h0;
                *(uint32_t*)(sm + OFF_FL + r0 * PITCH + c0 * 2)       = l0;
                *(uint32_t*)(sm + OFF_FH + (r0 + 8) * PITCH + c0 * 2) = h1v;
                *(uint32_t*)(sm + OFF_FL + (r0 + 8) * PITCH + c0 * 2) = l1v;
            }
        }
        __syncwarp();

        // ---- layer 2: K=128 (8 ksteps) ----------------------------------
#pragma unroll
        for (int nt = 0; nt < 16; nt++)
#pragma unroll
            for (int q = 0; q < 4; q++) d[nt][q] = 0.f;
        do_layer<8>(sm, OFF_FH, OFF_FL, OFF_W2H, OFF_W2L, wrow0, lane, d);

        // ---- epilogue 2: bias+relu, mask, column max --------------------
        {
            int cnt_w = __ldg(g_cnt + bc + (warp >> 2));
            int k0 = (wrow0 & 63) + (lane >> 2);
            bool va = k0 < cnt_w, vb = (k0 + 8) < cnt_w;
#pragma unroll
            for (int nt = 0; nt < 16; nt++) {
                int c0 = nt * 8 + (lane & 3) * 2;
                float m0 = fmaxf(va ? fmaxf(d[nt][0] + b2s[c0], 0.f) : 0.f,
                                 vb ? fmaxf(d[nt][2] + b2s[c0], 0.f) : 0.f);
                float m1 = fmaxf(va ? fmaxf(d[nt][1] + b2s[c0 + 1], 0.f) : 0.f,
                                 vb ? fmaxf(d[nt][3] + b2s[c0 + 1], 0.f) : 0.f);
#pragma unroll
                for (int o = 4; o <= 16; o <<= 1) {
                    m0 = fmaxf(m0, __shfl_xor_sync(0xffffffffu, m0, o));
                    m1 = fmaxf(m1, __shfl_xor_sync(0xffffffffu, m1, o));
                }
                if (lane < 4) {
                    wmx[warp * 128 + c0]     = m0;
                    wmx[warp * 128 + c0 + 1] = m1;
                }
            }
        }
        __syncthreads();
        {
            int col = tid & 127, ctr = tid >> 7;
            float mv = fmaxf(
                fmaxf(wmx[(ctr * 4 + 0) * 128 + col], wmx[(ctr * 4 + 1) * 128 + col]),
                fmaxf(wmx[(ctr * 4 + 2) * 128 + col], wmx[(ctr * 4 + 3) * 128 + col]));
            int cmo = bc + ctr;
            out[(size_t)cmo * Hd + col] = (__ldg(g_cnt + cmo) > 0) ? mv : 0.f;
        }
        __syncthreads();
    }
}

// ============================ launch ======================================
extern "C" void kernel_launch(void* const* d_in, const int* in_sizes, int n_in,
                              void* d_out, int out_size) {
    const float* x   = (const float*)d_in[0];
    const float* pos = (const float*)d_in[1];
    const float* W1  = (const float*)d_in[2];
    const float* b1  = (const float*)d_in[3];
    const float* W2  = (const float*)d_in[4];
    const float* b2  = (const float*)d_in[5];
    float* out = (float*)d_out;

    float* poss;
    if (out_size >= Bsz * Mc * (Hd + 3)) {
        poss = out + (size_t)Bsz * Mc * Hd;
    } else {
        void* tmp = nullptr;
        cudaGetSymbolAddress(&tmp, g_poss_dump);
        poss = (float*)tmp;
    }

    cudaFuncSetAttribute(mlp_kernel, cudaFuncAttributeMaxDynamicSharedMemorySize, MLP_SMEM);
    cudaFuncSetAttribute(fps_kernel, cudaFuncAttributeMaxDynamicSharedMemorySize, 3 * Npt * 4);

    fps_kernel<<<Bsz, FPS_T, 3 * Npt * 4>>>(pos);
    query_kernel<<<(Bsz * Mc) / QWARPS, QWARPS * 32>>>(pos, poss);
    mlp_kernel<<<152, 256, MLP_SMEM>>>(x, pos, W1, b1, W2, b2, out);
}